// round 1
// baseline (speedup 1.0000x reference)
#include <cuda_runtime.h>
#include <math.h>

#define HS   768
#define NH   12
#define HD   64
#define FF   3072
#define BB   4
#define SS   2048
#define MM   (BB*SS)     /* 8192 rows */
#define H3   (3*HS)      /* 2304 */

// ---------------- scratch (device globals, no allocation) ----------------
__device__ float g_qkv[(size_t)MM * H3];   // 75.5 MB
__device__ float g_ctx[(size_t)MM * HS];   // 25 MB
__device__ float g_ao [(size_t)MM * HS];   // 25 MB
__device__ float g_x1 [(size_t)MM * HS];   // 25 MB
__device__ float g_h1 [(size_t)MM * FF];   // 100 MB
__device__ float g_f2 [(size_t)MM * HS];   // 25 MB

// ---------------- GEMM: C = A[M,K] @ W[K,N] + bias, optional exact GELU ----
// BM=BN=128, BK=16, 256 threads, 8x8 micro-tile.
template<int GELU>
__global__ void __launch_bounds__(256, 2)
gemm_bias(const float* __restrict__ A, const float* __restrict__ W,
          const float* __restrict__ bias, float* __restrict__ C,
          int N, int K)
{
    __shared__ float As[16][128];
    __shared__ float Bs[16][128];

    const int tid = threadIdx.x;
    const int tx  = tid & 15;
    const int ty  = tid >> 4;
    const int row0 = blockIdx.y * 128;
    const int col0 = blockIdx.x * 128;

    const float* Ab = A + (size_t)row0 * K;
    const float* Wb = W + col0;

    float acc[8][8];
#pragma unroll
    for (int i = 0; i < 8; i++)
#pragma unroll
        for (int j = 0; j < 8; j++) acc[i][j] = 0.f;

    for (int k0 = 0; k0 < K; k0 += 16) {
        // A tile 128x16 -> As transposed [16][128]
#pragma unroll
        for (int it = 0; it < 2; it++) {
            int item = tid + it * 256;          // 0..511
            int r  = item >> 2;
            int c4 = item & 3;
            float4 v = *(const float4*)(Ab + (size_t)r * K + k0 + c4 * 4);
            As[c4*4+0][r] = v.x;
            As[c4*4+1][r] = v.y;
            As[c4*4+2][r] = v.z;
            As[c4*4+3][r] = v.w;
        }
        // B tile 16x128
#pragma unroll
        for (int it = 0; it < 2; it++) {
            int item = tid + it * 256;
            int r  = item >> 5;
            int c4 = item & 31;
            float4 v = *(const float4*)(Wb + (size_t)(k0 + r) * N + c4 * 4);
            *(float4*)(&Bs[r][c4 * 4]) = v;
        }
        __syncthreads();

#pragma unroll
        for (int kk = 0; kk < 16; kk++) {
            float a[8], b[8];
#pragma unroll
            for (int i = 0; i < 8; i++) a[i] = As[kk][ty * 8 + i];
#pragma unroll
            for (int j = 0; j < 8; j++) b[j] = Bs[kk][tx * 8 + j];
#pragma unroll
            for (int i = 0; i < 8; i++)
#pragma unroll
                for (int j = 0; j < 8; j++)
                    acc[i][j] = fmaf(a[i], b[j], acc[i][j]);
        }
        __syncthreads();
    }

#pragma unroll
    for (int i = 0; i < 8; i++) {
        int r = row0 + ty * 8 + i;
#pragma unroll
        for (int j = 0; j < 8; j++) {
            int c = col0 + tx * 8 + j;
            float v = acc[i][j] + bias[c];
            if (GELU)
                v = 0.5f * v * (1.0f + erff(v * 0.70710678118654752f));
            C[(size_t)r * N + c] = v;
        }
    }
}

// ---------------- fused flash-style attention ----------------------------
// grid (S/64, NH, B), 256 threads. Q tile 64 rows, KV tiles of 64.
// dynamic smem: Qs,Ks,Vs,Ps [64][65] + red[64][17] + m/l/alpha[64]
__global__ void __launch_bounds__(256, 2)
attn_kernel(const float* __restrict__ qkv, float* __restrict__ ctx)
{
    extern __shared__ float sm[];
    float* Qs   = sm;                 // 64*65
    float* Ks   = Qs  + 64 * 65;
    float* Vs   = Ks  + 64 * 65;
    float* Ps   = Vs  + 64 * 65;
    float* red  = Ps  + 64 * 65;      // 64*17
    float* mrow = red + 64 * 17;      // 64
    float* lrow = mrow + 64;          // 64
    float* arow = lrow + 64;          // 64

    const int tid = threadIdx.x;
    const int tx = tid & 15, ty = tid >> 4;
    const int r0 = ty * 4, c0 = tx * 4;
    const int qt = blockIdx.x, h = blockIdx.y, b = blockIdx.z;
    const int q0 = qt * 64;

    const float* Qg = qkv + ((size_t)(b * SS) + q0) * H3 + h * HD;
    const float* Kg = qkv + (size_t)(b * SS) * H3 + HS     + h * HD;
    const float* Vg = qkv + (size_t)(b * SS) * H3 + 2 * HS + h * HD;

    // load Q tile (64x64), 1024 float4, 4 per thread
#pragma unroll
    for (int it = 0; it < 4; it++) {
        int item = tid + it * 256;
        int r = item >> 4;
        int c4 = item & 15;
        float4 v = *(const float4*)(Qg + (size_t)r * H3 + c4 * 4);
        Qs[r * 65 + c4 * 4 + 0] = v.x;
        Qs[r * 65 + c4 * 4 + 1] = v.y;
        Qs[r * 65 + c4 * 4 + 2] = v.z;
        Qs[r * 65 + c4 * 4 + 3] = v.w;
    }
    if (tid < 64) { mrow[tid] = -1e30f; lrow[tid] = 0.f; }
    __syncthreads();

    float o[4][4];
#pragma unroll
    for (int i = 0; i < 4; i++)
#pragma unroll
        for (int j = 0; j < 4; j++) o[i][j] = 0.f;

    const float scale = 0.125f;   // 1/sqrt(64)

    for (int kt = 0; kt < SS / 64; kt++) {
        const float* Kt = Kg + (size_t)(kt * 64) * H3;
        const float* Vt = Vg + (size_t)(kt * 64) * H3;
#pragma unroll
        for (int it = 0; it < 4; it++) {
            int item = tid + it * 256;
            int r = item >> 4;
            int c4 = item & 15;
            float4 kv = *(const float4*)(Kt + (size_t)r * H3 + c4 * 4);
            Ks[r * 65 + c4 * 4 + 0] = kv.x;
            Ks[r * 65 + c4 * 4 + 1] = kv.y;
            Ks[r * 65 + c4 * 4 + 2] = kv.z;
            Ks[r * 65 + c4 * 4 + 3] = kv.w;
            float4 vv = *(const float4*)(Vt + (size_t)r * H3 + c4 * 4);
            Vs[r * 65 + c4 * 4 + 0] = vv.x;
            Vs[r * 65 + c4 * 4 + 1] = vv.y;
            Vs[r * 65 + c4 * 4 + 2] = vv.z;
            Vs[r * 65 + c4 * 4 + 3] = vv.w;
        }
        __syncthreads();

        // S tile = Q @ K^T  (4x4 per thread)
        float s[4][4];
#pragma unroll
        for (int i = 0; i < 4; i++)
#pragma unroll
            for (int j = 0; j < 4; j++) s[i][j] = 0.f;

        for (int d = 0; d < 64; d++) {
            float qa[4], kb[4];
#pragma unroll
            for (int i = 0; i < 4; i++) qa[i] = Qs[(r0 + i) * 65 + d];
#pragma unroll
            for (int j = 0; j < 4; j++) kb[j] = Ks[(c0 + j) * 65 + d];
#pragma unroll
            for (int i = 0; i < 4; i++)
#pragma unroll
                for (int j = 0; j < 4; j++)
                    s[i][j] = fmaf(qa[i], kb[j], s[i][j]);
        }
#pragma unroll
        for (int i = 0; i < 4; i++) {
            float pm = -1e30f;
#pragma unroll
            for (int j = 0; j < 4; j++) {
                s[i][j] *= scale;
                pm = fmaxf(pm, s[i][j]);
            }
            red[(r0 + i) * 17 + tx] = pm;
        }
        __syncthreads();

        if (tid < 64) {
            int r = tid;
            float mt = red[r * 17];
#pragma unroll
            for (int t = 1; t < 16; t++) mt = fmaxf(mt, red[r * 17 + t]);
            float mo = mrow[r];
            float mn = fmaxf(mo, mt);
            float al = __expf(mo - mn);
            mrow[r] = mn;
            arow[r] = al;
            lrow[r] *= al;
        }
        __syncthreads();

        // exponentiate, write P, partial row-sums, rescale O
#pragma unroll
        for (int i = 0; i < 4; i++) {
            float mn = mrow[r0 + i];
            float al = arow[r0 + i];
            float psum = 0.f;
#pragma unroll
            for (int j = 0; j < 4; j++) {
                float p = __expf(s[i][j] - mn);
                Ps[(r0 + i) * 65 + c0 + j] = p;
                psum += p;
            }
            red[(r0 + i) * 17 + tx] = psum;
#pragma unroll
            for (int j = 0; j < 4; j++) o[i][j] *= al;
        }
        __syncthreads();

        if (tid < 64) {
            int r = tid;
            float ssum = 0.f;
#pragma unroll
            for (int t = 0; t < 16; t++) ssum += red[r * 17 + t];
            lrow[r] += ssum;
        }

        // O += P @ V
        for (int j = 0; j < 64; j++) {
            float vb[4];
#pragma unroll
            for (int dd = 0; dd < 4; dd++) vb[dd] = Vs[j * 65 + c0 + dd];
#pragma unroll
            for (int i = 0; i < 4; i++) {
                float p = Ps[(r0 + i) * 65 + j];
#pragma unroll
                for (int dd = 0; dd < 4; dd++)
                    o[i][dd] = fmaf(p, vb[dd], o[i][dd]);
            }
        }
        __syncthreads();
    }

#pragma unroll
    for (int i = 0; i < 4; i++) {
        float inv = 1.0f / lrow[r0 + i];
        int q = q0 + r0 + i;
        float* dst = ctx + ((size_t)(b * SS) + q) * HS + h * HD + c0;
#pragma unroll
        for (int dd = 0; dd < 4; dd++) dst[dd] = o[i][dd] * inv;
    }
}

// ---------------- residual add + LayerNorm --------------------------------
__global__ void __launch_bounds__(256)
addln_kernel(const float* __restrict__ a, const float* __restrict__ res,
             const float* __restrict__ g, const float* __restrict__ bb,
             float* __restrict__ out)
{
    __shared__ float wsum[8], wsq[8];
    __shared__ float s_mu, s_rstd;

    const int row = blockIdx.x;
    const int tid = threadIdx.x;
    const float* ar = a   + (size_t)row * HS;
    const float* rr = res + (size_t)row * HS;

    float v[3];
    float sum = 0.f, sq = 0.f;
#pragma unroll
    for (int i = 0; i < 3; i++) {
        int idx = tid + i * 256;
        v[i] = ar[idx] + rr[idx];
        sum += v[i];
        sq  += v[i] * v[i];
    }
#pragma unroll
    for (int off = 16; off > 0; off >>= 1) {
        sum += __shfl_down_sync(0xffffffffu, sum, off);
        sq  += __shfl_down_sync(0xffffffffu, sq,  off);
    }
    if ((tid & 31) == 0) { wsum[tid >> 5] = sum; wsq[tid >> 5] = sq; }
    __syncthreads();
    if (tid == 0) {
        float s = 0.f, q = 0.f;
#pragma unroll
        for (int i = 0; i < 8; i++) { s += wsum[i]; q += wsq[i]; }
        float mu  = s * (1.f / HS);
        float var = q * (1.f / HS) - mu * mu;
        s_mu = mu;
        s_rstd = rsqrtf(fmaxf(var, 0.f) + 1e-12f);
    }
    __syncthreads();
    float mu = s_mu, rstd = s_rstd;
#pragma unroll
    for (int i = 0; i < 3; i++) {
        int idx = tid + i * 256;
        out[(size_t)row * HS + idx] = (v[i] - mu) * rstd * g[idx] + bb[idx];
    }
}

// ---------------- launch ---------------------------------------------------
extern "C" void kernel_launch(void* const* d_in, const int* in_sizes, int n_in,
                              void* d_out, int out_size)
{
    const float* x     = (const float*)d_in[0];
    const float* w_qkv = (const float*)d_in[1];
    const float* b_qkv = (const float*)d_in[2];
    const float* w_out = (const float*)d_in[3];
    const float* b_out = (const float*)d_in[4];
    const float* w_ff1 = (const float*)d_in[5];
    const float* b_ff1 = (const float*)d_in[6];
    const float* w_ff2 = (const float*)d_in[7];
    const float* b_ff2 = (const float*)d_in[8];
    const float* g1    = (const float*)d_in[9];
    const float* be1   = (const float*)d_in[10];
    const float* g2    = (const float*)d_in[11];
    const float* be2   = (const float*)d_in[12];
    float* out = (float*)d_out;

    float *qkv, *ctx, *ao, *x1, *h1, *f2;
    cudaGetSymbolAddress((void**)&qkv, g_qkv);
    cudaGetSymbolAddress((void**)&ctx, g_ctx);
    cudaGetSymbolAddress((void**)&ao,  g_ao);
    cudaGetSymbolAddress((void**)&x1,  g_x1);
    cudaGetSymbolAddress((void**)&h1,  g_h1);
    cudaGetSymbolAddress((void**)&f2,  g_f2);

    const int ATTN_SMEM = (4 * 64 * 65 + 64 * 17 + 3 * 64) * (int)sizeof(float);
    cudaFuncSetAttribute(attn_kernel,
                         cudaFuncAttributeMaxDynamicSharedMemorySize, ATTN_SMEM);

    // 1) QKV projection: [8192,768] @ [768,2304]
    gemm_bias<0><<<dim3(H3 / 128, MM / 128), 256>>>(x, w_qkv, b_qkv, qkv, H3, HS);

    // 2) fused attention -> ctx [8192,768]
    attn_kernel<<<dim3(SS / 64, NH, BB), 256, ATTN_SMEM>>>(qkv, ctx);

    // 3) output projection
    gemm_bias<0><<<dim3(HS / 128, MM / 128), 256>>>(ctx, w_out, b_out, ao, HS, HS);

    // 4) x1 = LN(x + attn_out)
    addln_kernel<<<MM, 256>>>(ao, x, g1, be1, x1);

    // 5) h = gelu(x1 @ w_ff1 + b_ff1)
    gemm_bias<1><<<dim3(FF / 128, MM / 128), 256>>>(x1, w_ff1, b_ff1, h1, FF, HS);

    // 6) ffn = h @ w_ff2 + b_ff2
    gemm_bias<0><<<dim3(HS / 128, MM / 128), 256>>>(h1, w_ff2, b_ff2, f2, HS, FF);

    // 7) out = LN(x1 + ffn)
    addln_kernel<<<MM, 256>>>(f2, x1, g2, be2, out);
}

// round 3
// speedup vs baseline: 1.5868x; 1.5868x over previous
#include <cuda_runtime.h>
#include <math.h>
#include <stdint.h>

#define HS   768
#define NH   12
#define HD   64
#define FF   3072
#define BB   4
#define SS   2048
#define MM   (BB*SS)     /* 8192 rows */
#define H3   (3*HS)      /* 2304 */

// ---------------- scratch (device globals, no allocation) ----------------
__device__ float g_qkv[(size_t)MM * H3];
__device__ float g_ctx[(size_t)MM * HS];
__device__ float g_ao [(size_t)MM * HS];
__device__ float g_x1 [(size_t)MM * HS];
__device__ float g_h1 [(size_t)MM * FF];
__device__ float g_f2 [(size_t)MM * HS];

// ---------------- tf32 mma.sync GEMM ---------------------------------------
// C[M,N] = A[M,K] @ W[K,N] + bias (+ exact GELU)
// BM=BN=128, BK=16, 256 threads (8 warps, 2x4), warp tile 64x32.
// mma.sync.aligned.m16n8k8.row.col.f32.tf32.tf32.f32
// SMEM tiles stored k-major with 132-float pitch (132 mod 32 == 4 -> fragment
// gathers across a warp touch 32 distinct banks).

#define GPITCH 132
#define GTILE  (16 * GPITCH)                 /* floats per stage tile */
#define GSMEM_FLOATS (4 * GTILE)             /* A0,A1,B0,B1 */
#define GSMEM_BYTES  (GSMEM_FLOATS * 4)

__device__ __forceinline__ uint32_t f2tf32(float v) {
    uint32_t u;
    asm("cvt.rn.tf32.f32 %0, %1;" : "=r"(u) : "f"(v));
    return u;
}

__device__ __forceinline__ void mma_tf32(float c[4], const uint32_t a[4], const uint32_t b[2]) {
    asm volatile(
        "mma.sync.aligned.m16n8k8.row.col.f32.tf32.tf32.f32 "
        "{%0,%1,%2,%3}, {%4,%5,%6,%7}, {%8,%9}, {%0,%1,%2,%3};"
        : "+f"(c[0]), "+f"(c[1]), "+f"(c[2]), "+f"(c[3])
        : "r"(a[0]), "r"(a[1]), "r"(a[2]), "r"(a[3]), "r"(b[0]), "r"(b[1]));
}

template<int GELU>
__global__ void __launch_bounds__(256)
gemm_mma(const float* __restrict__ A, const float* __restrict__ W,
         const float* __restrict__ bias, float* __restrict__ C,
         int N, int K)
{
    extern __shared__ float sm[];
    float* sA = sm;                 // [2][16][132]
    float* sB = sm + 2 * GTILE;     // [2][16][132]

    const int tid  = threadIdx.x;
    const int warp = tid >> 5;
    const int lane = tid & 31;
    const int g    = lane >> 2;     // 0..7
    const int t    = lane & 3;      // 0..3
    const int wm   = warp >> 2;     // 0..1 -> 64-row half
    const int wn   = warp & 3;      // 0..3 -> 32-col quarter
    const int row0 = blockIdx.y * 128;
    const int col0 = blockIdx.x * 128;

    // global-load coordinates (two items per thread per tile)
    const int ar[2]  = { (tid) >> 2,        (tid + 256) >> 2 };        // A row 0..127
    const int ac4[2] = { (tid) & 3,         (tid + 256) & 3 };         // A float4 col 0..3
    const int bkr[2] = { (tid) >> 5,        (tid + 256) >> 5 };        // B k-row 0..15
    const int bc4[2] = { (tid) & 31,        (tid + 256) & 31 };        // B float4 col 0..31

    float acc[4][4][4];
#pragma unroll
    for (int mi = 0; mi < 4; mi++)
#pragma unroll
        for (int ni = 0; ni < 4; ni++)
#pragma unroll
            for (int q = 0; q < 4; q++) acc[mi][ni][q] = 0.f;

    const int KT = K >> 4;
    float4 pa[2], pb[2];

    // prefetch tile 0
#pragma unroll
    for (int j = 0; j < 2; j++) {
        pa[j] = *(const float4*)(A + (size_t)(row0 + ar[j]) * K + ac4[j] * 4);
        pb[j] = *(const float4*)(W + (size_t)bkr[j] * N + col0 + bc4[j] * 4);
    }
    // stage tile 0
    {
        float* dA = sA;
        float* dB = sB;
#pragma unroll
        for (int j = 0; j < 2; j++) {
            dA[(ac4[j] * 4 + 0) * GPITCH + ar[j]] = __uint_as_float(f2tf32(pa[j].x));
            dA[(ac4[j] * 4 + 1) * GPITCH + ar[j]] = __uint_as_float(f2tf32(pa[j].y));
            dA[(ac4[j] * 4 + 2) * GPITCH + ar[j]] = __uint_as_float(f2tf32(pa[j].z));
            dA[(ac4[j] * 4 + 3) * GPITCH + ar[j]] = __uint_as_float(f2tf32(pa[j].w));
            uint4 u = make_uint4(f2tf32(pb[j].x), f2tf32(pb[j].y), f2tf32(pb[j].z), f2tf32(pb[j].w));
            *(uint4*)(dB + bkr[j] * GPITCH + bc4[j] * 4) = u;
        }
    }
    __syncthreads();

    for (int it = 0; it < KT; it++) {
        const int cur = it & 1;
        if (it + 1 < KT) {
            const int k0 = (it + 1) << 4;
#pragma unroll
            for (int j = 0; j < 2; j++) {
                pa[j] = *(const float4*)(A + (size_t)(row0 + ar[j]) * K + k0 + ac4[j] * 4);
                pb[j] = *(const float4*)(W + (size_t)(k0 + bkr[j]) * N + col0 + bc4[j] * 4);
            }
        }

        const float* cA = sA + cur * GTILE;
        const float* cB = sB + cur * GTILE;
#pragma unroll
        for (int ks = 0; ks < 2; ks++) {
            const int kb = ks * 8;
            uint32_t afr[4][4], bfr[4][2];
#pragma unroll
            for (int mi = 0; mi < 4; mi++) {
                const int m = wm * 64 + mi * 16 + g;
                afr[mi][0] = __float_as_uint(cA[(kb + t) * GPITCH + m]);
                afr[mi][1] = __float_as_uint(cA[(kb + t) * GPITCH + m + 8]);
                afr[mi][2] = __float_as_uint(cA[(kb + t + 4) * GPITCH + m]);
                afr[mi][3] = __float_as_uint(cA[(kb + t + 4) * GPITCH + m + 8]);
            }
#pragma unroll
            for (int ni = 0; ni < 4; ni++) {
                const int n = wn * 32 + ni * 8 + g;
                bfr[ni][0] = __float_as_uint(cB[(kb + t) * GPITCH + n]);
                bfr[ni][1] = __float_as_uint(cB[(kb + t + 4) * GPITCH + n]);
            }
#pragma unroll
            for (int mi = 0; mi < 4; mi++)
#pragma unroll
                for (int ni = 0; ni < 4; ni++)
                    mma_tf32(acc[mi][ni], afr[mi], bfr[ni]);
        }

        if (it + 1 < KT) {
            float* dA = sA + (cur ^ 1) * GTILE;
            float* dB = sB + (cur ^ 1) * GTILE;
#pragma unroll
            for (int j = 0; j < 2; j++) {
                dA[(ac4[j] * 4 + 0) * GPITCH + ar[j]] = __uint_as_float(f2tf32(pa[j].x));
                dA[(ac4[j] * 4 + 1) * GPITCH + ar[j]] = __uint_as_float(f2tf32(pa[j].y));
                dA[(ac4[j] * 4 + 2) * GPITCH + ar[j]] = __uint_as_float(f2tf32(pa[j].z));
                dA[(ac4[j] * 4 + 3) * GPITCH + ar[j]] = __uint_as_float(f2tf32(pa[j].w));
                uint4 u = make_uint4(f2tf32(pb[j].x), f2tf32(pb[j].y), f2tf32(pb[j].z), f2tf32(pb[j].w));
                *(uint4*)(dB + bkr[j] * GPITCH + bc4[j] * 4) = u;
            }
        }
        __syncthreads();
    }

    // epilogue
#pragma unroll
    for (int mi = 0; mi < 4; mi++) {
        const int r0 = row0 + wm * 64 + mi * 16 + g;
#pragma unroll
        for (int ni = 0; ni < 4; ni++) {
            const int c = col0 + wn * 32 + ni * 8 + 2 * t;
            const float b0 = __ldg(bias + c);
            const float b1 = __ldg(bias + c + 1);
            float v0 = acc[mi][ni][0] + b0;
            float v1 = acc[mi][ni][1] + b1;
            float v2 = acc[mi][ni][2] + b0;
            float v3 = acc[mi][ni][3] + b1;
            if (GELU) {
                v0 = 0.5f * v0 * (1.0f + erff(v0 * 0.70710678118654752f));
                v1 = 0.5f * v1 * (1.0f + erff(v1 * 0.70710678118654752f));
                v2 = 0.5f * v2 * (1.0f + erff(v2 * 0.70710678118654752f));
                v3 = 0.5f * v3 * (1.0f + erff(v3 * 0.70710678118654752f));
            }
            *(float2*)(C + (size_t)r0 * N + c)       = make_float2(v0, v1);
            *(float2*)(C + (size_t)(r0 + 8) * N + c) = make_float2(v2, v3);
        }
    }
}

// ---------------- fused flash-style attention (fp32) ----------------------
__global__ void __launch_bounds__(256, 2)
attn_kernel(const float* __restrict__ qkv, float* __restrict__ ctx)
{
    extern __shared__ float sm[];
    float* Qs   = sm;
    float* Ks   = Qs  + 64 * 65;
    float* Vs   = Ks  + 64 * 65;
    float* Ps   = Vs  + 64 * 65;
    float* red  = Ps  + 64 * 65;
    float* mrow = red + 64 * 17;
    float* lrow = mrow + 64;
    float* arow = lrow + 64;

    const int tid = threadIdx.x;
    const int tx = tid & 15, ty = tid >> 4;
    const int r0 = ty * 4, c0 = tx * 4;
    const int qt = blockIdx.x, h = blockIdx.y, b = blockIdx.z;
    const int q0 = qt * 64;

    const float* Qg = qkv + ((size_t)(b * SS) + q0) * H3 + h * HD;
    const float* Kg = qkv + (size_t)(b * SS) * H3 + HS     + h * HD;
    const float* Vg = qkv + (size_t)(b * SS) * H3 + 2 * HS + h * HD;

#pragma unroll
    for (int it = 0; it < 4; it++) {
        int item = tid + it * 256;
        int r = item >> 4;
        int c4 = item & 15;
        float4 v = *(const float4*)(Qg + (size_t)r * H3 + c4 * 4);
        Qs[r * 65 + c4 * 4 + 0] = v.x;
        Qs[r * 65 + c4 * 4 + 1] = v.y;
        Qs[r * 65 + c4 * 4 + 2] = v.z;
        Qs[r * 65 + c4 * 4 + 3] = v.w;
    }
    if (tid < 64) { mrow[tid] = -1e30f; lrow[tid] = 0.f; }
    __syncthreads();

    float o[4][4];
#pragma unroll
    for (int i = 0; i < 4; i++)
#pragma unroll
        for (int j = 0; j < 4; j++) o[i][j] = 0.f;

    const float scale = 0.125f;

    for (int kt = 0; kt < SS / 64; kt++) {
        const float* Kt = Kg + (size_t)(kt * 64) * H3;
        const float* Vt = Vg + (size_t)(kt * 64) * H3;
#pragma unroll
        for (int it = 0; it < 4; it++) {
            int item = tid + it * 256;
            int r = item >> 4;
            int c4 = item & 15;
            float4 kv = *(const float4*)(Kt + (size_t)r * H3 + c4 * 4);
            Ks[r * 65 + c4 * 4 + 0] = kv.x;
            Ks[r * 65 + c4 * 4 + 1] = kv.y;
            Ks[r * 65 + c4 * 4 + 2] = kv.z;
            Ks[r * 65 + c4 * 4 + 3] = kv.w;
            float4 vv = *(const float4*)(Vt + (size_t)r * H3 + c4 * 4);
            Vs[r * 65 + c4 * 4 + 0] = vv.x;
            Vs[r * 65 + c4 * 4 + 1] = vv.y;
            Vs[r * 65 + c4 * 4 + 2] = vv.z;
            Vs[r * 65 + c4 * 4 + 3] = vv.w;
        }
        __syncthreads();

        float s[4][4];
#pragma unroll
        for (int i = 0; i < 4; i++)
#pragma unroll
            for (int j = 0; j < 4; j++) s[i][j] = 0.f;

        for (int d = 0; d < 64; d++) {
            float qa[4], kb[4];
#pragma unroll
            for (int i = 0; i < 4; i++) qa[i] = Qs[(r0 + i) * 65 + d];
#pragma unroll
            for (int j = 0; j < 4; j++) kb[j] = Ks[(c0 + j) * 65 + d];
#pragma unroll
            for (int i = 0; i < 4; i++)
#pragma unroll
                for (int j = 0; j < 4; j++)
                    s[i][j] = fmaf(qa[i], kb[j], s[i][j]);
        }
#pragma unroll
        for (int i = 0; i < 4; i++) {
            float pm = -1e30f;
#pragma unroll
            for (int j = 0; j < 4; j++) {
                s[i][j] *= scale;
                pm = fmaxf(pm, s[i][j]);
            }
            red[(r0 + i) * 17 + tx] = pm;
        }
        __syncthreads();

        if (tid < 64) {
            int r = tid;
            float mt = red[r * 17];
#pragma unroll
            for (int tt = 1; tt < 16; tt++) mt = fmaxf(mt, red[r * 17 + tt]);
            float mo = mrow[r];
            float mn = fmaxf(mo, mt);
            float al = __expf(mo - mn);
            mrow[r] = mn;
            arow[r] = al;
            lrow[r] *= al;
        }
        __syncthreads();

#pragma unroll
        for (int i = 0; i < 4; i++) {
            float mn = mrow[r0 + i];
            float al = arow[r0 + i];
            float psum = 0.f;
#pragma unroll
            for (int j = 0; j < 4; j++) {
                float p = __expf(s[i][j] - mn);
                Ps[(r0 + i) * 65 + c0 + j] = p;
                psum += p;
            }
            red[(r0 + i) * 17 + tx] = psum;
#pragma unroll
            for (int j = 0; j < 4; j++) o[i][j] *= al;
        }
        __syncthreads();

        if (tid < 64) {
            int r = tid;
            float ssum = 0.f;
#pragma unroll
            for (int tt = 0; tt < 16; tt++) ssum += red[r * 17 + tt];
            lrow[r] += ssum;
        }

        for (int j = 0; j < 64; j++) {
            float vb[4];
#pragma unroll
            for (int dd = 0; dd < 4; dd++) vb[dd] = Vs[j * 65 + c0 + dd];
#pragma unroll
            for (int i = 0; i < 4; i++) {
                float p = Ps[(r0 + i) * 65 + j];
#pragma unroll
                for (int dd = 0; dd < 4; dd++)
                    o[i][dd] = fmaf(p, vb[dd], o[i][dd]);
            }
        }
        __syncthreads();
    }

#pragma unroll
    for (int i = 0; i < 4; i++) {
        float inv = 1.0f / lrow[r0 + i];
        int q = q0 + r0 + i;
        float* dst = ctx + ((size_t)(b * SS) + q) * HS + h * HD + c0;
#pragma unroll
        for (int dd = 0; dd < 4; dd++) dst[dd] = o[i][dd] * inv;
    }
}

// ---------------- residual add + LayerNorm --------------------------------
__global__ void __launch_bounds__(256)
addln_kernel(const float* __restrict__ a, const float* __restrict__ res,
             const float* __restrict__ g, const float* __restrict__ bb,
             float* __restrict__ out)
{
    __shared__ float wsum[8], wsq[8];
    __shared__ float s_mu, s_rstd;

    const int row = blockIdx.x;
    const int tid = threadIdx.x;
    const float* ar = a   + (size_t)row * HS;
    const float* rr = res + (size_t)row * HS;

    float v[3];
    float sum = 0.f, sq = 0.f;
#pragma unroll
    for (int i = 0; i < 3; i++) {
        int idx = tid + i * 256;
        v[i] = ar[idx] + rr[idx];
        sum += v[i];
        sq  += v[i] * v[i];
    }
#pragma unroll
    for (int off = 16; off > 0; off >>= 1) {
        sum += __shfl_down_sync(0xffffffffu, sum, off);
        sq  += __shfl_down_sync(0xffffffffu, sq,  off);
    }
    if ((tid & 31) == 0) { wsum[tid >> 5] = sum; wsq[tid >> 5] = sq; }
    __syncthreads();
    if (tid == 0) {
        float s = 0.f, q = 0.f;
#pragma unroll
        for (int i = 0; i < 8; i++) { s += wsum[i]; q += wsq[i]; }
        float mu  = s * (1.f / HS);
        float var = q * (1.f / HS) - mu * mu;
        s_mu = mu;
        s_rstd = rsqrtf(fmaxf(var, 0.f) + 1e-12f);
    }
    __syncthreads();
    float mu = s_mu, rstd = s_rstd;
#pragma unroll
    for (int i = 0; i < 3; i++) {
        int idx = tid + i * 256;
        out[(size_t)row * HS + idx] = (v[i] - mu) * rstd * g[idx] + bb[idx];
    }
}

// ---------------- launch ---------------------------------------------------
extern "C" void kernel_launch(void* const* d_in, const int* in_sizes, int n_in,
                              void* d_out, int out_size)
{
    const float* x     = (const float*)d_in[0];
    const float* w_qkv = (const float*)d_in[1];
    const float* b_qkv = (const float*)d_in[2];
    const float* w_out = (const float*)d_in[3];
    const float* b_out = (const float*)d_in[4];
    const float* w_ff1 = (const float*)d_in[5];
    const float* b_ff1 = (const float*)d_in[6];
    const float* w_ff2 = (const float*)d_in[7];
    const float* b_ff2 = (const float*)d_in[8];
    const float* g1    = (const float*)d_in[9];
    const float* be1   = (const float*)d_in[10];
    const float* g2    = (const float*)d_in[11];
    const float* be2   = (const float*)d_in[12];
    float* out = (float*)d_out;

    float *qkv, *ctx, *ao, *x1, *h1, *f2;
    cudaGetSymbolAddress((void**)&qkv, g_qkv);
    cudaGetSymbolAddress((void**)&ctx, g_ctx);
    cudaGetSymbolAddress((void**)&ao,  g_ao);
    cudaGetSymbolAddress((void**)&x1,  g_x1);
    cudaGetSymbolAddress((void**)&h1,  g_h1);
    cudaGetSymbolAddress((void**)&f2,  g_f2);

    const int ATTN_SMEM = (4 * 64 * 65 + 64 * 17 + 3 * 64) * (int)sizeof(float);
    cudaFuncSetAttribute(attn_kernel,
                         cudaFuncAttributeMaxDynamicSharedMemorySize, ATTN_SMEM);

    // 1) QKV projection: [8192,768] @ [768,2304]
    gemm_mma<0><<<dim3(H3 / 128, MM / 128), 256, GSMEM_BYTES>>>(x, w_qkv, b_qkv, qkv, H3, HS);

    // 2) fused attention
    attn_kernel<<<dim3(SS / 64, NH, BB), 256, ATTN_SMEM>>>(qkv, ctx);

    // 3) output projection
    gemm_mma<0><<<dim3(HS / 128, MM / 128), 256, GSMEM_BYTES>>>(ctx, w_out, b_out, ao, HS, HS);

    // 4) x1 = LN(x + attn_out)
    addln_kernel<<<MM, 256>>>(ao, x, g1, be1, x1);

    // 5) h = gelu(x1 @ w_ff1 + b_ff1)
    gemm_mma<1><<<dim3(FF / 128, MM / 128), 256, GSMEM_BYTES>>>(x1, w_ff1, b_ff1, h1, FF, HS);

    // 6) ffn = h @ w_ff2 + b_ff2
    gemm_mma<0><<<dim3(HS / 128, MM / 128), 256, GSMEM_BYTES>>>(h1, w_ff2, b_ff2, f2, HS, FF);

    // 7) out = LN(x1 + ffn)
    addln_kernel<<<MM, 256>>>(f2, x1, g2, be2, out);
}

// round 4
// speedup vs baseline: 2.6056x; 1.6420x over previous
#include <cuda_runtime.h>
#include <math.h>
#include <stdint.h>

#define HS   768
#define NH   12
#define HD   64
#define FF   3072
#define BB   4
#define SS   2048
#define MM   (BB*SS)     /* 8192 rows */
#define H3   (3*HS)      /* 2304 */

// ---------------- scratch (device globals, no allocation) ----------------
__device__ float g_qkv[(size_t)MM * H3];
__device__ float g_ctx[(size_t)MM * HS];
__device__ float g_ao [(size_t)MM * HS];
__device__ float g_x1 [(size_t)MM * HS];
__device__ float g_h1 [(size_t)MM * FF];
__device__ float g_f2 [(size_t)MM * HS];

__device__ __forceinline__ uint32_t f2tf32(float v) {
    uint32_t u;
    asm("cvt.rn.tf32.f32 %0, %1;" : "=r"(u) : "f"(v));
    return u;
}

__device__ __forceinline__ void mma_tf32(float c[4], const uint32_t a[4], const uint32_t b[2]) {
    asm volatile(
        "mma.sync.aligned.m16n8k8.row.col.f32.tf32.tf32.f32 "
        "{%0,%1,%2,%3}, {%4,%5,%6,%7}, {%8,%9}, {%0,%1,%2,%3};"
        : "+f"(c[0]), "+f"(c[1]), "+f"(c[2]), "+f"(c[3])
        : "r"(a[0]), "r"(a[1]), "r"(a[2]), "r"(a[3]), "r"(b[0]), "r"(b[1]));
}

// ---------------- tf32 mma.sync GEMM (unchanged from R3) -------------------
#define GPITCH 132
#define GTILE  (16 * GPITCH)
#define GSMEM_FLOATS (4 * GTILE)
#define GSMEM_BYTES  (GSMEM_FLOATS * 4)

template<int GELU>
__global__ void __launch_bounds__(256)
gemm_mma(const float* __restrict__ A, const float* __restrict__ W,
         const float* __restrict__ bias, float* __restrict__ C,
         int N, int K)
{
    extern __shared__ float sm[];
    float* sA = sm;
    float* sB = sm + 2 * GTILE;

    const int tid  = threadIdx.x;
    const int warp = tid >> 5;
    const int lane = tid & 31;
    const int g    = lane >> 2;
    const int t    = lane & 3;
    const int wm   = warp >> 2;
    const int wn   = warp & 3;
    const int row0 = blockIdx.y * 128;
    const int col0 = blockIdx.x * 128;

    const int ar[2]  = { (tid) >> 2,        (tid + 256) >> 2 };
    const int ac4[2] = { (tid) & 3,         (tid + 256) & 3 };
    const int bkr[2] = { (tid) >> 5,        (tid + 256) >> 5 };
    const int bc4[2] = { (tid) & 31,        (tid + 256) & 31 };

    float acc[4][4][4];
#pragma unroll
    for (int mi = 0; mi < 4; mi++)
#pragma unroll
        for (int ni = 0; ni < 4; ni++)
#pragma unroll
            for (int q = 0; q < 4; q++) acc[mi][ni][q] = 0.f;

    const int KT = K >> 4;
    float4 pa[2], pb[2];

#pragma unroll
    for (int j = 0; j < 2; j++) {
        pa[j] = *(const float4*)(A + (size_t)(row0 + ar[j]) * K + ac4[j] * 4);
        pb[j] = *(const float4*)(W + (size_t)bkr[j] * N + col0 + bc4[j] * 4);
    }
    {
        float* dA = sA;
        float* dB = sB;
#pragma unroll
        for (int j = 0; j < 2; j++) {
            dA[(ac4[j] * 4 + 0) * GPITCH + ar[j]] = __uint_as_float(f2tf32(pa[j].x));
            dA[(ac4[j] * 4 + 1) * GPITCH + ar[j]] = __uint_as_float(f2tf32(pa[j].y));
            dA[(ac4[j] * 4 + 2) * GPITCH + ar[j]] = __uint_as_float(f2tf32(pa[j].z));
            dA[(ac4[j] * 4 + 3) * GPITCH + ar[j]] = __uint_as_float(f2tf32(pa[j].w));
            uint4 u = make_uint4(f2tf32(pb[j].x), f2tf32(pb[j].y), f2tf32(pb[j].z), f2tf32(pb[j].w));
            *(uint4*)(dB + bkr[j] * GPITCH + bc4[j] * 4) = u;
        }
    }
    __syncthreads();

    for (int it = 0; it < KT; it++) {
        const int cur = it & 1;
        if (it + 1 < KT) {
            const int k0 = (it + 1) << 4;
#pragma unroll
            for (int j = 0; j < 2; j++) {
                pa[j] = *(const float4*)(A + (size_t)(row0 + ar[j]) * K + k0 + ac4[j] * 4);
                pb[j] = *(const float4*)(W + (size_t)(k0 + bkr[j]) * N + col0 + bc4[j] * 4);
            }
        }

        const float* cA = sA + cur * GTILE;
        const float* cB = sB + cur * GTILE;
#pragma unroll
        for (int ks = 0; ks < 2; ks++) {
            const int kb = ks * 8;
            uint32_t afr[4][4], bfr[4][2];
#pragma unroll
            for (int mi = 0; mi < 4; mi++) {
                const int m = wm * 64 + mi * 16 + g;
                afr[mi][0] = __float_as_uint(cA[(kb + t) * GPITCH + m]);
                afr[mi][1] = __float_as_uint(cA[(kb + t) * GPITCH + m + 8]);
                afr[mi][2] = __float_as_uint(cA[(kb + t + 4) * GPITCH + m]);
                afr[mi][3] = __float_as_uint(cA[(kb + t + 4) * GPITCH + m + 8]);
            }
#pragma unroll
            for (int ni = 0; ni < 4; ni++) {
                const int n = wn * 32 + ni * 8 + g;
                bfr[ni][0] = __float_as_uint(cB[(kb + t) * GPITCH + n]);
                bfr[ni][1] = __float_as_uint(cB[(kb + t + 4) * GPITCH + n]);
            }
#pragma unroll
            for (int mi = 0; mi < 4; mi++)
#pragma unroll
                for (int ni = 0; ni < 4; ni++)
                    mma_tf32(acc[mi][ni], afr[mi], bfr[ni]);
        }

        if (it + 1 < KT) {
            float* dA = sA + (cur ^ 1) * GTILE;
            float* dB = sB + (cur ^ 1) * GTILE;
#pragma unroll
            for (int j = 0; j < 2; j++) {
                dA[(ac4[j] * 4 + 0) * GPITCH + ar[j]] = __uint_as_float(f2tf32(pa[j].x));
                dA[(ac4[j] * 4 + 1) * GPITCH + ar[j]] = __uint_as_float(f2tf32(pa[j].y));
                dA[(ac4[j] * 4 + 2) * GPITCH + ar[j]] = __uint_as_float(f2tf32(pa[j].z));
                dA[(ac4[j] * 4 + 3) * GPITCH + ar[j]] = __uint_as_float(f2tf32(pa[j].w));
                uint4 u = make_uint4(f2tf32(pb[j].x), f2tf32(pb[j].y), f2tf32(pb[j].z), f2tf32(pb[j].w));
                *(uint4*)(dB + bkr[j] * GPITCH + bc4[j] * 4) = u;
            }
        }
        __syncthreads();
    }

#pragma unroll
    for (int mi = 0; mi < 4; mi++) {
        const int r0 = row0 + wm * 64 + mi * 16 + g;
#pragma unroll
        for (int ni = 0; ni < 4; ni++) {
            const int c = col0 + wn * 32 + ni * 8 + 2 * t;
            const float b0 = __ldg(bias + c);
            const float b1 = __ldg(bias + c + 1);
            float v0 = acc[mi][ni][0] + b0;
            float v1 = acc[mi][ni][1] + b1;
            float v2 = acc[mi][ni][2] + b0;
            float v3 = acc[mi][ni][3] + b1;
            if (GELU) {
                v0 = 0.5f * v0 * (1.0f + erff(v0 * 0.70710678118654752f));
                v1 = 0.5f * v1 * (1.0f + erff(v1 * 0.70710678118654752f));
                v2 = 0.5f * v2 * (1.0f + erff(v2 * 0.70710678118654752f));
                v3 = 0.5f * v3 * (1.0f + erff(v3 * 0.70710678118654752f));
            }
            *(float2*)(C + (size_t)r0 * N + c)       = make_float2(v0, v1);
            *(float2*)(C + (size_t)(r0 + 8) * N + c) = make_float2(v2, v3);
        }
    }
}

// ---------------- tensor-core flash attention ------------------------------
// grid (SS/128, NH, BB), 256 threads (8 warps x 16 q-rows).
// SMEM: sK [64][68] (j-major), sV [64][72] (j-major), sP [128][68] (aliases sQ).
#define QPITCH 68
#define KPITCH 68
#define VPITCH 72
#define ATTN_SMEM_FLOATS (64 * KPITCH + 64 * VPITCH + 128 * QPITCH)
#define ATTN_SMEM_BYTES  (ATTN_SMEM_FLOATS * 4)

__global__ void __launch_bounds__(256)
attn_mma(const float* __restrict__ qkv, float* __restrict__ ctx)
{
    extern __shared__ float sm[];
    float* sK = sm;                       // [64][68]
    float* sV = sK + 64 * KPITCH;         // [64][72]
    float* sP = sV + 64 * VPITCH;         // [128][68], aliases sQ
    float* sQ = sP;

    const int tid  = threadIdx.x;
    const int warp = tid >> 5;
    const int lane = tid & 31;
    const int g    = lane >> 2;
    const int t    = lane & 3;
    const int m0   = warp * 16;

    const int q0 = blockIdx.x * 128;
    const int h  = blockIdx.y;
    const int b  = blockIdx.z;

    const float* Qg = qkv + ((size_t)(b * SS) + q0) * H3 + h * HD;
    const float* Kg = qkv + (size_t)(b * SS) * H3 + HS     + h * HD;
    const float* Vg = qkv + (size_t)(b * SS) * H3 + 2 * HS + h * HD;

    // stage Q (128x64), tf32-rounded
#pragma unroll
    for (int it = 0; it < 8; it++) {
        int item = tid + it * 256;
        int r = item >> 4, c = item & 15;
        float4 v = *(const float4*)(Qg + (size_t)r * H3 + c * 4);
        uint4 u = make_uint4(f2tf32(v.x), f2tf32(v.y), f2tf32(v.z), f2tf32(v.w));
        *(uint4*)(sQ + r * QPITCH + c * 4) = u;
    }
    __syncthreads();

    // extract Q fragments (register-resident for whole kernel)
    uint32_t qf[8][4];
#pragma unroll
    for (int kb = 0; kb < 8; kb++) {
        qf[kb][0] = __float_as_uint(sQ[(m0 + g)     * QPITCH + kb * 8 + t]);
        qf[kb][1] = __float_as_uint(sQ[(m0 + g + 8) * QPITCH + kb * 8 + t]);
        qf[kb][2] = __float_as_uint(sQ[(m0 + g)     * QPITCH + kb * 8 + t + 4]);
        qf[kb][3] = __float_as_uint(sQ[(m0 + g + 8) * QPITCH + kb * 8 + t + 4]);
    }

    float mrow0 = -1e30f, mrow1 = -1e30f;
    float lrow0 = 0.f,    lrow1 = 0.f;
    float o[8][4];
#pragma unroll
    for (int ni = 0; ni < 8; ni++)
#pragma unroll
        for (int q = 0; q < 4; q++) o[ni][q] = 0.f;

    const float scale = 0.125f;

    for (int kt = 0; kt < SS / 64; kt++) {
        __syncthreads();   // prior tile fully consumed (also covers sQ->sP handoff)
        // load K, V tiles (64 x 64 each), tf32-rounded, j-major
#pragma unroll
        for (int it = 0; it < 4; it++) {
            int item = tid + it * 256;
            int j = item >> 4, c = item & 15;
            const size_t go = (size_t)(kt * 64 + j) * H3 + c * 4;
            float4 kv = *(const float4*)(Kg + go);
            uint4 uk = make_uint4(f2tf32(kv.x), f2tf32(kv.y), f2tf32(kv.z), f2tf32(kv.w));
            *(uint4*)(sK + j * KPITCH + c * 4) = uk;
            float4 vv = *(const float4*)(Vg + go);
            uint4 uv = make_uint4(f2tf32(vv.x), f2tf32(vv.y), f2tf32(vv.z), f2tf32(vv.w));
            *(uint4*)(sV + j * VPITCH + c * 4) = uv;
        }
        __syncthreads();

        // S = Q @ K^T  -> s_[ni][4]
        float s_[8][4];
#pragma unroll
        for (int ni = 0; ni < 8; ni++)
#pragma unroll
            for (int q = 0; q < 4; q++) s_[ni][q] = 0.f;

#pragma unroll
        for (int kb = 0; kb < 8; kb++) {
#pragma unroll
            for (int ni = 0; ni < 8; ni++) {
                uint32_t bf[2];
                bf[0] = __float_as_uint(sK[(ni * 8 + g) * KPITCH + kb * 8 + t]);
                bf[1] = __float_as_uint(sK[(ni * 8 + g) * KPITCH + kb * 8 + t + 4]);
                mma_tf32(s_[ni], qf[kb], bf);
            }
        }

        // online softmax
        float mn0 = -1e30f, mn1 = -1e30f;
#pragma unroll
        for (int ni = 0; ni < 8; ni++) {
            s_[ni][0] *= scale; s_[ni][1] *= scale;
            s_[ni][2] *= scale; s_[ni][3] *= scale;
            mn0 = fmaxf(mn0, fmaxf(s_[ni][0], s_[ni][1]));
            mn1 = fmaxf(mn1, fmaxf(s_[ni][2], s_[ni][3]));
        }
        mn0 = fmaxf(mn0, __shfl_xor_sync(0xffffffffu, mn0, 1));
        mn0 = fmaxf(mn0, __shfl_xor_sync(0xffffffffu, mn0, 2));
        mn1 = fmaxf(mn1, __shfl_xor_sync(0xffffffffu, mn1, 1));
        mn1 = fmaxf(mn1, __shfl_xor_sync(0xffffffffu, mn1, 2));

        const float mnew0 = fmaxf(mrow0, mn0);
        const float mnew1 = fmaxf(mrow1, mn1);
        const float a0 = __expf(mrow0 - mnew0);
        const float a1 = __expf(mrow1 - mnew1);
        mrow0 = mnew0; mrow1 = mnew1;

        float ladd0 = 0.f, ladd1 = 0.f;
#pragma unroll
        for (int ni = 0; ni < 8; ni++) {
            float p00 = __expf(s_[ni][0] - mnew0);
            float p01 = __expf(s_[ni][1] - mnew0);
            float p10 = __expf(s_[ni][2] - mnew1);
            float p11 = __expf(s_[ni][3] - mnew1);
            ladd0 += p00 + p01;
            ladd1 += p10 + p11;
            *(float2*)(sP + (m0 + g)     * QPITCH + ni * 8 + 2 * t) = make_float2(p00, p01);
            *(float2*)(sP + (m0 + g + 8) * QPITCH + ni * 8 + 2 * t) = make_float2(p10, p11);
            o[ni][0] *= a0; o[ni][1] *= a0;
            o[ni][2] *= a1; o[ni][3] *= a1;
        }
        ladd0 += __shfl_xor_sync(0xffffffffu, ladd0, 1);
        ladd0 += __shfl_xor_sync(0xffffffffu, ladd0, 2);
        ladd1 += __shfl_xor_sync(0xffffffffu, ladd1, 1);
        ladd1 += __shfl_xor_sync(0xffffffffu, ladd1, 2);
        lrow0 = lrow0 * a0 + ladd0;
        lrow1 = lrow1 * a1 + ladd1;

        __syncwarp();   // sP writes visible within warp

        // O += P @ V
#pragma unroll
        for (int kb = 0; kb < 8; kb++) {
            uint32_t af[4];
            af[0] = __float_as_uint(sP[(m0 + g)     * QPITCH + kb * 8 + t]);
            af[1] = __float_as_uint(sP[(m0 + g + 8) * QPITCH + kb * 8 + t]);
            af[2] = __float_as_uint(sP[(m0 + g)     * QPITCH + kb * 8 + t + 4]);
            af[3] = __float_as_uint(sP[(m0 + g + 8) * QPITCH + kb * 8 + t + 4]);
#pragma unroll
            for (int ni = 0; ni < 8; ni++) {
                uint32_t bf[2];
                bf[0] = __float_as_uint(sV[(kb * 8 + t)     * VPITCH + ni * 8 + g]);
                bf[1] = __float_as_uint(sV[(kb * 8 + t + 4) * VPITCH + ni * 8 + g]);
                mma_tf32(o[ni], af, bf);
            }
        }
    }

    // finalize and write ctx
    const float inv0 = 1.0f / lrow0;
    const float inv1 = 1.0f / lrow1;
    const int qr0 = q0 + m0 + g;
    float* dst0 = ctx + ((size_t)(b * SS) + qr0)     * HS + h * HD;
    float* dst1 = ctx + ((size_t)(b * SS) + qr0 + 8) * HS + h * HD;
#pragma unroll
    for (int ni = 0; ni < 8; ni++) {
        const int c = ni * 8 + 2 * t;
        *(float2*)(dst0 + c) = make_float2(o[ni][0] * inv0, o[ni][1] * inv0);
        *(float2*)(dst1 + c) = make_float2(o[ni][2] * inv1, o[ni][3] * inv1);
    }
}

// ---------------- residual add + LayerNorm --------------------------------
__global__ void __launch_bounds__(256)
addln_kernel(const float* __restrict__ a, const float* __restrict__ res,
             const float* __restrict__ g, const float* __restrict__ bb,
             float* __restrict__ out)
{
    __shared__ float wsum[8], wsq[8];
    __shared__ float s_mu, s_rstd;

    const int row = blockIdx.x;
    const int tid = threadIdx.x;
    const float* ar = a   + (size_t)row * HS;
    const float* rr = res + (size_t)row * HS;

    float v[3];
    float sum = 0.f, sq = 0.f;
#pragma unroll
    for (int i = 0; i < 3; i++) {
        int idx = tid + i * 256;
        v[i] = ar[idx] + rr[idx];
        sum += v[i];
        sq  += v[i] * v[i];
    }
#pragma unroll
    for (int off = 16; off > 0; off >>= 1) {
        sum += __shfl_down_sync(0xffffffffu, sum, off);
        sq  += __shfl_down_sync(0xffffffffu, sq,  off);
    }
    if ((tid & 31) == 0) { wsum[tid >> 5] = sum; wsq[tid >> 5] = sq; }
    __syncthreads();
    if (tid == 0) {
        float s = 0.f, q = 0.f;
#pragma unroll
        for (int i = 0; i < 8; i++) { s += wsum[i]; q += wsq[i]; }
        float mu  = s * (1.f / HS);
        float var = q * (1.f / HS) - mu * mu;
        s_mu = mu;
        s_rstd = rsqrtf(fmaxf(var, 0.f) + 1e-12f);
    }
    __syncthreads();
    float mu = s_mu, rstd = s_rstd;
#pragma unroll
    for (int i = 0; i < 3; i++) {
        int idx = tid + i * 256;
        out[(size_t)row * HS + idx] = (v[i] - mu) * rstd * g[idx] + bb[idx];
    }
}

// ---------------- launch ---------------------------------------------------
extern "C" void kernel_launch(void* const* d_in, const int* in_sizes, int n_in,
                              void* d_out, int out_size)
{
    const float* x     = (const float*)d_in[0];
    const float* w_qkv = (const float*)d_in[1];
    const float* b_qkv = (const float*)d_in[2];
    const float* w_out = (const float*)d_in[3];
    const float* b_out = (const float*)d_in[4];
    const float* w_ff1 = (const float*)d_in[5];
    const float* b_ff1 = (const float*)d_in[6];
    const float* w_ff2 = (const float*)d_in[7];
    const float* b_ff2 = (const float*)d_in[8];
    const float* g1    = (const float*)d_in[9];
    const float* be1   = (const float*)d_in[10];
    const float* g2    = (const float*)d_in[11];
    const float* be2   = (const float*)d_in[12];
    float* out = (float*)d_out;

    float *qkv, *ctx, *ao, *x1, *h1, *f2;
    cudaGetSymbolAddress((void**)&qkv, g_qkv);
    cudaGetSymbolAddress((void**)&ctx, g_ctx);
    cudaGetSymbolAddress((void**)&ao,  g_ao);
    cudaGetSymbolAddress((void**)&x1,  g_x1);
    cudaGetSymbolAddress((void**)&h1,  g_h1);
    cudaGetSymbolAddress((void**)&f2,  g_f2);

    cudaFuncSetAttribute(attn_mma,
                         cudaFuncAttributeMaxDynamicSharedMemorySize, ATTN_SMEM_BYTES);

    // 1) QKV projection: [8192,768] @ [768,2304]
    gemm_mma<0><<<dim3(H3 / 128, MM / 128), 256, GSMEM_BYTES>>>(x, w_qkv, b_qkv, qkv, H3, HS);

    // 2) fused tensor-core flash attention
    attn_mma<<<dim3(SS / 128, NH, BB), 256, ATTN_SMEM_BYTES>>>(qkv, ctx);

    // 3) output projection
    gemm_mma<0><<<dim3(HS / 128, MM / 128), 256, GSMEM_BYTES>>>(ctx, w_out, b_out, ao, HS, HS);

    // 4) x1 = LN(x + attn_out)
    addln_kernel<<<MM, 256>>>(ao, x, g1, be1, x1);

    // 5) h = gelu(x1 @ w_ff1 + b_ff1)
    gemm_mma<1><<<dim3(FF / 128, MM / 128), 256, GSMEM_BYTES>>>(x1, w_ff1, b_ff1, h1, FF, HS);

    // 6) ffn = h @ w_ff2 + b_ff2
    gemm_mma<0><<<dim3(HS / 128, MM / 128), 256, GSMEM_BYTES>>>(h1, w_ff2, b_ff2, f2, HS, FF);

    // 7) out = LN(x1 + ffn)
    addln_kernel<<<MM, 256>>>(f2, x1, g2, be2, out);
}

// round 5
// speedup vs baseline: 4.7828x; 1.8356x over previous
#include <cuda_runtime.h>
#include <cuda_fp16.h>
#include <math.h>
#include <stdint.h>

#define HS   768
#define NH   12
#define HD   64
#define FF   3072
#define BB   4
#define SS   2048
#define MM   (BB*SS)     /* 8192 rows */
#define H3   (3*HS)      /* 2304 */

// ---------------- scratch (device globals, no allocation) ----------------
__device__ __half g_xh   [(size_t)MM * HS];
__device__ __half g_wqkvT[(size_t)H3 * HS];
__device__ __half g_woutT[(size_t)HS * HS];
__device__ __half g_wff1T[(size_t)FF * HS];
__device__ __half g_wff2T[(size_t)HS * FF];
__device__ __half g_qkvh [(size_t)MM * H3];
__device__ __half g_ctxh [(size_t)MM * HS];
__device__ float  g_ao   [(size_t)MM * HS];
__device__ float  g_x1   [(size_t)MM * HS];
__device__ __half g_x1h  [(size_t)MM * HS];
__device__ __half g_h1h  [(size_t)MM * FF];
__device__ float  g_f2   [(size_t)MM * HS];

// ================= helpers ==================================================
__device__ __forceinline__ uint32_t smem_u32(const void* p) {
    uint32_t a;
    asm("{ .reg .u64 t; cvta.to.shared.u64 t, %1; cvt.u32.u64 %0, t; }" : "=r"(a) : "l"(p));
    return a;
}
__device__ __forceinline__ void cp16(uint32_t s, const void* g) {
    asm volatile("cp.async.cg.shared.global [%0], [%1], 16;" :: "r"(s), "l"(g) : "memory");
}
__device__ __forceinline__ void cp_commit() {
    asm volatile("cp.async.commit_group;" ::: "memory");
}
template<int N> __device__ __forceinline__ void cp_wait() {
    asm volatile("cp.async.wait_group %0;" :: "n"(N) : "memory");
}
__device__ __forceinline__ void mma_f16(float c[4], const uint32_t a[4], const uint32_t b[2]) {
    asm volatile(
        "mma.sync.aligned.m16n8k16.row.col.f32.f16.f16.f32 "
        "{%0,%1,%2,%3}, {%4,%5,%6,%7}, {%8,%9}, {%0,%1,%2,%3};"
        : "+f"(c[0]), "+f"(c[1]), "+f"(c[2]), "+f"(c[3])
        : "r"(a[0]), "r"(a[1]), "r"(a[2]), "r"(a[3]), "r"(b[0]), "r"(b[1]));
}
__device__ __forceinline__ void mma_tf32(float c[4], const uint32_t a[4], const uint32_t b[2]) {
    asm volatile(
        "mma.sync.aligned.m16n8k8.row.col.f32.tf32.tf32.f32 "
        "{%0,%1,%2,%3}, {%4,%5,%6,%7}, {%8,%9}, {%0,%1,%2,%3};"
        : "+f"(c[0]), "+f"(c[1]), "+f"(c[2]), "+f"(c[3])
        : "r"(a[0]), "r"(a[1]), "r"(a[2]), "r"(a[3]), "r"(b[0]), "r"(b[1]));
}

// ---------------- pre-pass: fp32 -> fp16 ----------------------------------
__global__ void __launch_bounds__(256)
f2h_kernel(const float* __restrict__ in, __half* __restrict__ out, int n4)
{
    int i = blockIdx.x * 256 + threadIdx.x;
    if (i < n4) {
        float4 v = *(const float4*)(in + (size_t)i * 4);
        __half2 h0 = __floats2half2_rn(v.x, v.y);
        __half2 h1 = __floats2half2_rn(v.z, v.w);
        *(uint2*)(out + (size_t)i * 4) = make_uint2(*(uint32_t*)&h0, *(uint32_t*)&h1);
    }
}

// W[K][N] fp32 -> WT[N][K] fp16.  grid (N/32, K/32), block (32,8)
__global__ void __launch_bounds__(256)
transpose_h(const float* __restrict__ W, __half* __restrict__ WT, int K, int N)
{
    __shared__ float t[32][33];
    const int n0 = blockIdx.x * 32, k0 = blockIdx.y * 32;
    const int tx = threadIdx.x, ty = threadIdx.y;
#pragma unroll
    for (int i = 0; i < 4; i++)
        t[ty + i * 8][tx] = W[(size_t)(k0 + ty + i * 8) * N + n0 + tx];
    __syncthreads();
#pragma unroll
    for (int i = 0; i < 4; i++)
        WT[(size_t)(n0 + ty + i * 8) * K + k0 + tx] = __float2half_rn(t[tx][ty + i * 8]);
}

// ---------------- fp16 mma GEMM --------------------------------------------
// C[M,N] = A[M,K](h) @ WT[N,K](h)^T + bias; optional exact GELU; fp32/fp16 out.
// BM=BN=128, BK=32, 256 threads (8 warps 2x4, warp tile 64x32), 4-stage cp.async.
#define PITCH  40                       /* halfs per 32-half row (+8 pad) */
#define AST    (128 * PITCH)            /* halfs per A stage */
#define STG_H  (2 * AST)                /* halfs per stage (A+B) */
#define STAGES 4
#define GH_SMEM_BYTES (STAGES * STG_H * 2)

template<int GELU, int OUTH>
__global__ void __launch_bounds__(256, 2)
gemm_h(const __half* __restrict__ A, const __half* __restrict__ WT,
       const float* __restrict__ bias,
       float* __restrict__ Cf, __half* __restrict__ Ch,
       int N, int K)
{
    extern __shared__ __half hsm[];
    const uint32_t sbase = smem_u32(hsm);

    const int tid  = threadIdx.x;
    const int warp = tid >> 5;
    const int lane = tid & 31;
    const int g    = lane >> 2;
    const int t    = lane & 3;
    const int wm   = warp >> 2;
    const int wn   = warp & 3;
    const int row0 = blockIdx.y * 128;
    const int col0 = blockIdx.x * 128;
    const int KT   = K >> 5;

    const __half* Ab = A  + (size_t)row0 * K;
    const __half* Bb = WT + (size_t)col0 * K;

    const int cr = tid >> 2;        // 0..63  (x2 rows via +64)
    const int cc = tid & 3;         // chunk 0..3

    float acc[4][4][4];
#pragma unroll
    for (int mi = 0; mi < 4; mi++)
#pragma unroll
        for (int ni = 0; ni < 4; ni++)
#pragma unroll
            for (int q = 0; q < 4; q++) acc[mi][ni][q] = 0.f;

    // prologue: issue stages 0..2
#pragma unroll
    for (int s = 0; s < 3; s++) {
        const uint32_t sa = sbase + s * STG_H * 2;
        const int k0 = s * 32;
#pragma unroll
        for (int j = 0; j < 2; j++) {
            int r = cr + j * 64;
            cp16(sa + (r * PITCH + cc * 8) * 2,            Ab + (size_t)r * K + k0 + cc * 8);
            cp16(sa + (AST + r * PITCH + cc * 8) * 2,      Bb + (size_t)r * K + k0 + cc * 8);
        }
        cp_commit();
    }

    for (int it = 0; it < KT; it++) {
        if (it + 2 < KT)      cp_wait<2>();
        else if (it + 1 < KT) cp_wait<1>();
        else                  cp_wait<0>();
        __syncthreads();

        if (it + 3 < KT) {
            const int s = (it + 3) & 3;
            const uint32_t sa = sbase + s * STG_H * 2;
            const int k0 = (it + 3) * 32;
#pragma unroll
            for (int j = 0; j < 2; j++) {
                int r = cr + j * 64;
                cp16(sa + (r * PITCH + cc * 8) * 2,       Ab + (size_t)r * K + k0 + cc * 8);
                cp16(sa + (AST + r * PITCH + cc * 8) * 2, Bb + (size_t)r * K + k0 + cc * 8);
            }
            cp_commit();
        }

        const __half* cA = hsm + (size_t)(it & 3) * STG_H;
        const __half* cB = cA + AST;
#pragma unroll
        for (int ks = 0; ks < 2; ks++) {
            const int kb = ks * 16;
            uint32_t af[4][4], bf[4][2];
#pragma unroll
            for (int mi = 0; mi < 4; mi++) {
                const int m = wm * 64 + mi * 16 + g;
                af[mi][0] = *(const uint32_t*)(cA + m * PITCH + kb + 2 * t);
                af[mi][1] = *(const uint32_t*)(cA + (m + 8) * PITCH + kb + 2 * t);
                af[mi][2] = *(const uint32_t*)(cA + m * PITCH + kb + 8 + 2 * t);
                af[mi][3] = *(const uint32_t*)(cA + (m + 8) * PITCH + kb + 8 + 2 * t);
            }
#pragma unroll
            for (int ni = 0; ni < 4; ni++) {
                const int n = wn * 32 + ni * 8 + g;
                bf[ni][0] = *(const uint32_t*)(cB + n * PITCH + kb + 2 * t);
                bf[ni][1] = *(const uint32_t*)(cB + n * PITCH + kb + 8 + 2 * t);
            }
#pragma unroll
            for (int mi = 0; mi < 4; mi++)
#pragma unroll
                for (int ni = 0; ni < 4; ni++)
                    mma_f16(acc[mi][ni], af[mi], bf[ni]);
        }
    }

    // epilogue
#pragma unroll
    for (int mi = 0; mi < 4; mi++) {
        const int r0 = row0 + wm * 64 + mi * 16 + g;
#pragma unroll
        for (int ni = 0; ni < 4; ni++) {
            const int c = col0 + wn * 32 + ni * 8 + 2 * t;
            const float b0 = __ldg(bias + c);
            const float b1 = __ldg(bias + c + 1);
            float v0 = acc[mi][ni][0] + b0;
            float v1 = acc[mi][ni][1] + b1;
            float v2 = acc[mi][ni][2] + b0;
            float v3 = acc[mi][ni][3] + b1;
            if (GELU) {
                v0 = 0.5f * v0 * (1.0f + erff(v0 * 0.70710678118654752f));
                v1 = 0.5f * v1 * (1.0f + erff(v1 * 0.70710678118654752f));
                v2 = 0.5f * v2 * (1.0f + erff(v2 * 0.70710678118654752f));
                v3 = 0.5f * v3 * (1.0f + erff(v3 * 0.70710678118654752f));
            }
            if (OUTH) {
                __half2 h0 = __floats2half2_rn(v0, v1);
                __half2 h1 = __floats2half2_rn(v2, v3);
                *(__half2*)(Ch + (size_t)r0 * N + c)       = h0;
                *(__half2*)(Ch + (size_t)(r0 + 8) * N + c) = h1;
            } else {
                *(float2*)(Cf + (size_t)r0 * N + c)       = make_float2(v0, v1);
                *(float2*)(Cf + (size_t)(r0 + 8) * N + c) = make_float2(v2, v3);
            }
        }
    }
}

// ---------------- tensor-core flash attention (fp16 in/out, tf32 mma) ------
#define QPITCH 68
#define KPITCH 68
#define VPITCH 72
#define ATTN_SMEM_FLOATS (64 * KPITCH + 64 * VPITCH + 128 * QPITCH)
#define ATTN_SMEM_BYTES  (ATTN_SMEM_FLOATS * 4)

__device__ __forceinline__ void h8_to_smem(float* dst, const __half* src) {
    uint4 u = *(const uint4*)(src);
    const __half2* hp = (const __half2*)&u;
#pragma unroll
    for (int q = 0; q < 4; q++) {
        float2 f = __half22float2(hp[q]);
        dst[2 * q]     = f.x;
        dst[2 * q + 1] = f.y;
    }
}

__global__ void __launch_bounds__(256)
attn_mma(const __half* __restrict__ qkvh, __half* __restrict__ ctxh)
{
    extern __shared__ float sm[];
    float* sK = sm;                       // [64][68]
    float* sV = sK + 64 * KPITCH;         // [64][72]
    float* sP = sV + 64 * VPITCH;         // [128][68], aliases sQ
    float* sQ = sP;

    const int tid  = threadIdx.x;
    const int warp = tid >> 5;
    const int lane = tid & 31;
    const int g    = lane >> 2;
    const int t    = lane & 3;
    const int m0   = warp * 16;

    const int q0 = blockIdx.x * 128;
    const int h  = blockIdx.y;
    const int b  = blockIdx.z;

    const __half* Qg = qkvh + ((size_t)(b * SS) + q0) * H3 + h * HD;
    const __half* Kg = qkvh + (size_t)(b * SS) * H3 + HS     + h * HD;
    const __half* Vg = qkvh + (size_t)(b * SS) * H3 + 2 * HS + h * HD;

    // stage Q (128x64)
#pragma unroll
    for (int it = 0; it < 4; it++) {
        int item = tid + it * 256;
        int r = item >> 3, c = item & 7;
        h8_to_smem(sQ + r * QPITCH + c * 8, Qg + (size_t)r * H3 + c * 8);
    }
    __syncthreads();

    uint32_t qf[8][4];
#pragma unroll
    for (int kb = 0; kb < 8; kb++) {
        qf[kb][0] = __float_as_uint(sQ[(m0 + g)     * QPITCH + kb * 8 + t]);
        qf[kb][1] = __float_as_uint(sQ[(m0 + g + 8) * QPITCH + kb * 8 + t]);
        qf[kb][2] = __float_as_uint(sQ[(m0 + g)     * QPITCH + kb * 8 + t + 4]);
        qf[kb][3] = __float_as_uint(sQ[(m0 + g + 8) * QPITCH + kb * 8 + t + 4]);
    }

    float mrow0 = -1e30f, mrow1 = -1e30f;
    float lrow0 = 0.f,    lrow1 = 0.f;
    float o[8][4];
#pragma unroll
    for (int ni = 0; ni < 8; ni++)
#pragma unroll
        for (int q = 0; q < 4; q++) o[ni][q] = 0.f;

    const float scale = 0.125f;

    for (int kt = 0; kt < SS / 64; kt++) {
        __syncthreads();
#pragma unroll
        for (int it = 0; it < 2; it++) {
            int item = tid + it * 256;
            int j = item >> 3, c = item & 7;
            const size_t go = (size_t)(kt * 64 + j) * H3 + c * 8;
            h8_to_smem(sK + j * KPITCH + c * 8, Kg + go);
            h8_to_smem(sV + j * VPITCH + c * 8, Vg + go);
        }
        __syncthreads();

        float s_[8][4];
#pragma unroll
        for (int ni = 0; ni < 8; ni++)
#pragma unroll
            for (int q = 0; q < 4; q++) s_[ni][q] = 0.f;

#pragma unroll
        for (int kb = 0; kb < 8; kb++) {
#pragma unroll
            for (int ni = 0; ni < 8; ni++) {
                uint32_t bf[2];
                bf[0] = __float_as_uint(sK[(ni * 8 + g) * KPITCH + kb * 8 + t]);
                bf[1] = __float_as_uint(sK[(ni * 8 + g) * KPITCH + kb * 8 + t + 4]);
                mma_tf32(s_[ni], qf[kb], bf);
            }
        }

        float mn0 = -1e30f, mn1 = -1e30f;
#pragma unroll
        for (int ni = 0; ni < 8; ni++) {
            s_[ni][0] *= scale; s_[ni][1] *= scale;
            s_[ni][2] *= scale; s_[ni][3] *= scale;
            mn0 = fmaxf(mn0, fmaxf(s_[ni][0], s_[ni][1]));
            mn1 = fmaxf(mn1, fmaxf(s_[ni][2], s_[ni][3]));
        }
        mn0 = fmaxf(mn0, __shfl_xor_sync(0xffffffffu, mn0, 1));
        mn0 = fmaxf(mn0, __shfl_xor_sync(0xffffffffu, mn0, 2));
        mn1 = fmaxf(mn1, __shfl_xor_sync(0xffffffffu, mn1, 1));
        mn1 = fmaxf(mn1, __shfl_xor_sync(0xffffffffu, mn1, 2));

        const float mnew0 = fmaxf(mrow0, mn0);
        const float mnew1 = fmaxf(mrow1, mn1);
        const float a0 = __expf(mrow0 - mnew0);
        const float a1 = __expf(mrow1 - mnew1);
        mrow0 = mnew0; mrow1 = mnew1;

        float ladd0 = 0.f, ladd1 = 0.f;
#pragma unroll
        for (int ni = 0; ni < 8; ni++) {
            float p00 = __expf(s_[ni][0] - mnew0);
            float p01 = __expf(s_[ni][1] - mnew0);
            float p10 = __expf(s_[ni][2] - mnew1);
            float p11 = __expf(s_[ni][3] - mnew1);
            ladd0 += p00 + p01;
            ladd1 += p10 + p11;
            *(float2*)(sP + (m0 + g)     * QPITCH + ni * 8 + 2 * t) = make_float2(p00, p01);
            *(float2*)(sP + (m0 + g + 8) * QPITCH + ni * 8 + 2 * t) = make_float2(p10, p11);
            o[ni][0] *= a0; o[ni][1] *= a0;
            o[ni][2] *= a1; o[ni][3] *= a1;
        }
        ladd0 += __shfl_xor_sync(0xffffffffu, ladd0, 1);
        ladd0 += __shfl_xor_sync(0xffffffffu, ladd0, 2);
        ladd1 += __shfl_xor_sync(0xffffffffu, ladd1, 1);
        ladd1 += __shfl_xor_sync(0xffffffffu, ladd1, 2);
        lrow0 = lrow0 * a0 + ladd0;
        lrow1 = lrow1 * a1 + ladd1;

        __syncwarp();

#pragma unroll
        for (int kb = 0; kb < 8; kb++) {
            uint32_t af[4];
            af[0] = __float_as_uint(sP[(m0 + g)     * QPITCH + kb * 8 + t]);
            af[1] = __float_as_uint(sP[(m0 + g + 8) * QPITCH + kb * 8 + t]);
            af[2] = __float_as_uint(sP[(m0 + g)     * QPITCH + kb * 8 + t + 4]);
            af[3] = __float_as_uint(sP[(m0 + g + 8) * QPITCH + kb * 8 + t + 4]);
#pragma unroll
            for (int ni = 0; ni < 8; ni++) {
                uint32_t bf[2];
                bf[0] = __float_as_uint(sV[(kb * 8 + t)     * VPITCH + ni * 8 + g]);
                bf[1] = __float_as_uint(sV[(kb * 8 + t + 4) * VPITCH + ni * 8 + g]);
                mma_tf32(o[ni], af, bf);
            }
        }
    }

    const float inv0 = 1.0f / lrow0;
    const float inv1 = 1.0f / lrow1;
    const int qr0 = q0 + m0 + g;
    __half* dst0 = ctxh + ((size_t)(b * SS) + qr0)     * HS + h * HD;
    __half* dst1 = ctxh + ((size_t)(b * SS) + qr0 + 8) * HS + h * HD;
#pragma unroll
    for (int ni = 0; ni < 8; ni++) {
        const int c = ni * 8 + 2 * t;
        *(__half2*)(dst0 + c) = __floats2half2_rn(o[ni][0] * inv0, o[ni][1] * inv0);
        *(__half2*)(dst1 + c) = __floats2half2_rn(o[ni][2] * inv1, o[ni][3] * inv1);
    }
}

// ---------------- residual add + LayerNorm --------------------------------
template<int WH>
__global__ void __launch_bounds__(256)
addln_kernel(const float* __restrict__ a, const float* __restrict__ res,
             const float* __restrict__ g, const float* __restrict__ bb,
             float* __restrict__ outf, __half* __restrict__ outh)
{
    __shared__ float wsum[8], wsq[8];
    __shared__ float s_mu, s_rstd;

    const int row = blockIdx.x;
    const int tid = threadIdx.x;
    const float* ar = a   + (size_t)row * HS;
    const float* rr = res + (size_t)row * HS;

    float v[3];
    float sum = 0.f, sq = 0.f;
#pragma unroll
    for (int i = 0; i < 3; i++) {
        int idx = tid + i * 256;
        v[i] = ar[idx] + rr[idx];
        sum += v[i];
        sq  += v[i] * v[i];
    }
#pragma unroll
    for (int off = 16; off > 0; off >>= 1) {
        sum += __shfl_down_sync(0xffffffffu, sum, off);
        sq  += __shfl_down_sync(0xffffffffu, sq,  off);
    }
    if ((tid & 31) == 0) { wsum[tid >> 5] = sum; wsq[tid >> 5] = sq; }
    __syncthreads();
    if (tid == 0) {
        float s = 0.f, q = 0.f;
#pragma unroll
        for (int i = 0; i < 8; i++) { s += wsum[i]; q += wsq[i]; }
        float mu  = s * (1.f / HS);
        float var = q * (1.f / HS) - mu * mu;
        s_mu = mu;
        s_rstd = rsqrtf(fmaxf(var, 0.f) + 1e-12f);
    }
    __syncthreads();
    float mu = s_mu, rstd = s_rstd;
#pragma unroll
    for (int i = 0; i < 3; i++) {
        int idx = tid + i * 256;
        float r = (v[i] - mu) * rstd * g[idx] + bb[idx];
        outf[(size_t)row * HS + idx] = r;
        if (WH) outh[(size_t)row * HS + idx] = __float2half_rn(r);
    }
}

// ---------------- launch ---------------------------------------------------
extern "C" void kernel_launch(void* const* d_in, const int* in_sizes, int n_in,
                              void* d_out, int out_size)
{
    const float* x     = (const float*)d_in[0];
    const float* w_qkv = (const float*)d_in[1];
    const float* b_qkv = (const float*)d_in[2];
    const float* w_out = (const float*)d_in[3];
    const float* b_out = (const float*)d_in[4];
    const float* w_ff1 = (const float*)d_in[5];
    const float* b_ff1 = (const float*)d_in[6];
    const float* w_ff2 = (const float*)d_in[7];
    const float* b_ff2 = (const float*)d_in[8];
    const float* g1    = (const float*)d_in[9];
    const float* be1   = (const float*)d_in[10];
    const float* g2    = (const float*)d_in[11];
    const float* be2   = (const float*)d_in[12];
    float* out = (float*)d_out;

    __half *xh, *wqkvT, *woutT, *wff1T, *wff2T, *qkvh, *ctxh, *x1h, *h1h;
    float *ao, *x1, *f2;
    cudaGetSymbolAddress((void**)&xh,    g_xh);
    cudaGetSymbolAddress((void**)&wqkvT, g_wqkvT);
    cudaGetSymbolAddress((void**)&woutT, g_woutT);
    cudaGetSymbolAddress((void**)&wff1T, g_wff1T);
    cudaGetSymbolAddress((void**)&wff2T, g_wff2T);
    cudaGetSymbolAddress((void**)&qkvh,  g_qkvh);
    cudaGetSymbolAddress((void**)&ctxh,  g_ctxh);
    cudaGetSymbolAddress((void**)&x1h,   g_x1h);
    cudaGetSymbolAddress((void**)&h1h,   g_h1h);
    cudaGetSymbolAddress((void**)&ao,    g_ao);
    cudaGetSymbolAddress((void**)&x1,    g_x1);
    cudaGetSymbolAddress((void**)&f2,    g_f2);

    cudaFuncSetAttribute(attn_mma,
                         cudaFuncAttributeMaxDynamicSharedMemorySize, ATTN_SMEM_BYTES);
    cudaFuncSetAttribute(gemm_h<0,0>, cudaFuncAttributeMaxDynamicSharedMemorySize, GH_SMEM_BYTES);
    cudaFuncSetAttribute(gemm_h<0,1>, cudaFuncAttributeMaxDynamicSharedMemorySize, GH_SMEM_BYTES);
    cudaFuncSetAttribute(gemm_h<1,1>, cudaFuncAttributeMaxDynamicSharedMemorySize, GH_SMEM_BYTES);

    dim3 tb(32, 8);

    // pre-pass: fp16 input + transposed fp16 weights
    f2h_kernel<<<(MM * HS / 4 + 255) / 256, 256>>>(x, xh, MM * HS / 4);
    transpose_h<<<dim3(H3 / 32, HS / 32), tb>>>(w_qkv, wqkvT, HS, H3);
    transpose_h<<<dim3(HS / 32, HS / 32), tb>>>(w_out, woutT, HS, HS);
    transpose_h<<<dim3(FF / 32, HS / 32), tb>>>(w_ff1, wff1T, HS, FF);
    transpose_h<<<dim3(HS / 32, FF / 32), tb>>>(w_ff2, wff2T, FF, HS);

    // 1) QKV projection -> fp16 qkv
    gemm_h<0,1><<<dim3(H3 / 128, MM / 128), 256, GH_SMEM_BYTES>>>(
        xh, wqkvT, b_qkv, nullptr, qkvh, H3, HS);

    // 2) fused flash attention -> fp16 ctx
    attn_mma<<<dim3(SS / 128, NH, BB), 256, ATTN_SMEM_BYTES>>>(qkvh, ctxh);

    // 3) output projection -> fp32 ao
    gemm_h<0,0><<<dim3(HS / 128, MM / 128), 256, GH_SMEM_BYTES>>>(
        ctxh, woutT, b_out, ao, nullptr, HS, HS);

    // 4) x1 = LN(x + ao), dual write fp32 + fp16
    addln_kernel<1><<<MM, 256>>>(ao, x, g1, be1, x1, x1h);

    // 5) h1 = gelu(x1 @ w_ff1 + b_ff1) -> fp16
    gemm_h<1,1><<<dim3(FF / 128, MM / 128), 256, GH_SMEM_BYTES>>>(
        x1h, wff1T, b_ff1, nullptr, h1h, FF, HS);

    // 6) f2 = h1 @ w_ff2 + b_ff2 -> fp32
    gemm_h<0,0><<<dim3(HS / 128, MM / 128), 256, GH_SMEM_BYTES>>>(
        h1h, wff2T, b_ff2, f2, nullptr, HS, FF);

    // 7) out = LN(x1 + f2)
    addln_kernel<0><<<MM, 256>>>(f2, x1, g2, be2, out, nullptr);
}

// round 6
// speedup vs baseline: 6.1017x; 1.2757x over previous
#include <cuda_runtime.h>
#include <cuda_fp16.h>
#include <math.h>
#include <stdint.h>

#define HS   768
#define NH   12
#define HD   64
#define FF   3072
#define BB   4
#define SS   2048
#define MM   (BB*SS)     /* 8192 rows */
#define H3   (3*HS)      /* 2304 */

// ---------------- scratch (device globals, no allocation) ----------------
__device__ __half g_xh   [(size_t)MM * HS];
__device__ __half g_wqkvT[(size_t)H3 * HS];
__device__ __half g_woutT[(size_t)HS * HS];
__device__ __half g_wff1T[(size_t)FF * HS];
__device__ __half g_wff2T[(size_t)HS * FF];
__device__ __half g_qkvh [(size_t)MM * H3];
__device__ __half g_ctxh [(size_t)MM * HS];
__device__ float  g_ao   [(size_t)MM * HS];
__device__ float  g_x1   [(size_t)MM * HS];
__device__ __half g_x1h  [(size_t)MM * HS];
__device__ __half g_h1h  [(size_t)MM * FF];
__device__ float  g_f2   [(size_t)MM * HS];

// ================= helpers ==================================================
__device__ __forceinline__ uint32_t smem_u32(const void* p) {
    uint32_t a;
    asm("{ .reg .u64 t; cvta.to.shared.u64 t, %1; cvt.u32.u64 %0, t; }" : "=r"(a) : "l"(p));
    return a;
}
__device__ __forceinline__ void cp16(uint32_t s, const void* g) {
    asm volatile("cp.async.cg.shared.global [%0], [%1], 16;" :: "r"(s), "l"(g) : "memory");
}
__device__ __forceinline__ void cp_commit() {
    asm volatile("cp.async.commit_group;" ::: "memory");
}
template<int N> __device__ __forceinline__ void cp_wait() {
    asm volatile("cp.async.wait_group %0;" :: "n"(N) : "memory");
}
__device__ __forceinline__ void mma_f16(float c[4], const uint32_t a[4], const uint32_t b[2]) {
    asm volatile(
        "mma.sync.aligned.m16n8k16.row.col.f32.f16.f16.f32 "
        "{%0,%1,%2,%3}, {%4,%5,%6,%7}, {%8,%9}, {%0,%1,%2,%3};"
        : "+f"(c[0]), "+f"(c[1]), "+f"(c[2]), "+f"(c[3])
        : "r"(a[0]), "r"(a[1]), "r"(a[2]), "r"(a[3]), "r"(b[0]), "r"(b[1]));
}
__device__ __forceinline__ void ldmx2t(uint32_t& b0, uint32_t& b1, uint32_t addr) {
    asm volatile("ldmatrix.sync.aligned.m8n8.x2.trans.shared.b16 {%0,%1}, [%2];"
                 : "=r"(b0), "=r"(b1) : "r"(addr));
}

// ---------------- pre-pass: fp32 -> fp16 ----------------------------------
__global__ void __launch_bounds__(256)
f2h_kernel(const float* __restrict__ in, __half* __restrict__ out, int n4)
{
    int i = blockIdx.x * 256 + threadIdx.x;
    if (i < n4) {
        float4 v = *(const float4*)(in + (size_t)i * 4);
        __half2 h0 = __floats2half2_rn(v.x, v.y);
        __half2 h1 = __floats2half2_rn(v.z, v.w);
        *(uint2*)(out + (size_t)i * 4) = make_uint2(*(uint32_t*)&h0, *(uint32_t*)&h1);
    }
}

// W[K][N] fp32 -> WT[N][K] fp16.  grid (N/32, K/32), block (32,8)
__global__ void __launch_bounds__(256)
transpose_h(const float* __restrict__ W, __half* __restrict__ WT, int K, int N)
{
    __shared__ float t[32][33];
    const int n0 = blockIdx.x * 32, k0 = blockIdx.y * 32;
    const int tx = threadIdx.x, ty = threadIdx.y;
#pragma unroll
    for (int i = 0; i < 4; i++)
        t[ty + i * 8][tx] = W[(size_t)(k0 + ty + i * 8) * N + n0 + tx];
    __syncthreads();
#pragma unroll
    for (int i = 0; i < 4; i++)
        WT[(size_t)(n0 + ty + i * 8) * K + k0 + tx] = __float2half_rn(t[tx][ty + i * 8]);
}

// ---------------- fp16 mma GEMM (unchanged from R5) ------------------------
#define PITCH  40
#define AST    (128 * PITCH)
#define STG_H  (2 * AST)
#define STAGES 4
#define GH_SMEM_BYTES (STAGES * STG_H * 2)

template<int GELU, int OUTH>
__global__ void __launch_bounds__(256, 2)
gemm_h(const __half* __restrict__ A, const __half* __restrict__ WT,
       const float* __restrict__ bias,
       float* __restrict__ Cf, __half* __restrict__ Ch,
       int N, int K)
{
    extern __shared__ __half hsm[];
    const uint32_t sbase = smem_u32(hsm);

    const int tid  = threadIdx.x;
    const int warp = tid >> 5;
    const int lane = tid & 31;
    const int g    = lane >> 2;
    const int t    = lane & 3;
    const int wm   = warp >> 2;
    const int wn   = warp & 3;
    const int row0 = blockIdx.y * 128;
    const int col0 = blockIdx.x * 128;
    const int KT   = K >> 5;

    const __half* Ab = A  + (size_t)row0 * K;
    const __half* Bb = WT + (size_t)col0 * K;

    const int cr = tid >> 2;
    const int cc = tid & 3;

    float acc[4][4][4];
#pragma unroll
    for (int mi = 0; mi < 4; mi++)
#pragma unroll
        for (int ni = 0; ni < 4; ni++)
#pragma unroll
            for (int q = 0; q < 4; q++) acc[mi][ni][q] = 0.f;

#pragma unroll
    for (int s = 0; s < 3; s++) {
        const uint32_t sa = sbase + s * STG_H * 2;
        const int k0 = s * 32;
#pragma unroll
        for (int j = 0; j < 2; j++) {
            int r = cr + j * 64;
            cp16(sa + (r * PITCH + cc * 8) * 2,       Ab + (size_t)r * K + k0 + cc * 8);
            cp16(sa + (AST + r * PITCH + cc * 8) * 2, Bb + (size_t)r * K + k0 + cc * 8);
        }
        cp_commit();
    }

    for (int it = 0; it < KT; it++) {
        if (it + 2 < KT)      cp_wait<2>();
        else if (it + 1 < KT) cp_wait<1>();
        else                  cp_wait<0>();
        __syncthreads();

        if (it + 3 < KT) {
            const int s = (it + 3) & 3;
            const uint32_t sa = sbase + s * STG_H * 2;
            const int k0 = (it + 3) * 32;
#pragma unroll
            for (int j = 0; j < 2; j++) {
                int r = cr + j * 64;
                cp16(sa + (r * PITCH + cc * 8) * 2,       Ab + (size_t)r * K + k0 + cc * 8);
                cp16(sa + (AST + r * PITCH + cc * 8) * 2, Bb + (size_t)r * K + k0 + cc * 8);
            }
            cp_commit();
        }

        const __half* cA = hsm + (size_t)(it & 3) * STG_H;
        const __half* cB = cA + AST;
#pragma unroll
        for (int ks = 0; ks < 2; ks++) {
            const int kb = ks * 16;
            uint32_t af[4][4], bf[4][2];
#pragma unroll
            for (int mi = 0; mi < 4; mi++) {
                const int m = wm * 64 + mi * 16 + g;
                af[mi][0] = *(const uint32_t*)(cA + m * PITCH + kb + 2 * t);
                af[mi][1] = *(const uint32_t*)(cA + (m + 8) * PITCH + kb + 2 * t);
                af[mi][2] = *(const uint32_t*)(cA + m * PITCH + kb + 8 + 2 * t);
                af[mi][3] = *(const uint32_t*)(cA + (m + 8) * PITCH + kb + 8 + 2 * t);
            }
#pragma unroll
            for (int ni = 0; ni < 4; ni++) {
                const int n = wn * 32 + ni * 8 + g;
                bf[ni][0] = *(const uint32_t*)(cB + n * PITCH + kb + 2 * t);
                bf[ni][1] = *(const uint32_t*)(cB + n * PITCH + kb + 8 + 2 * t);
            }
#pragma unroll
            for (int mi = 0; mi < 4; mi++)
#pragma unroll
                for (int ni = 0; ni < 4; ni++)
                    mma_f16(acc[mi][ni], af[mi], bf[ni]);
        }
    }

#pragma unroll
    for (int mi = 0; mi < 4; mi++) {
        const int r0 = row0 + wm * 64 + mi * 16 + g;
#pragma unroll
        for (int ni = 0; ni < 4; ni++) {
            const int c = col0 + wn * 32 + ni * 8 + 2 * t;
            const float b0 = __ldg(bias + c);
            const float b1 = __ldg(bias + c + 1);
            float v0 = acc[mi][ni][0] + b0;
            float v1 = acc[mi][ni][1] + b1;
            float v2 = acc[mi][ni][2] + b0;
            float v3 = acc[mi][ni][3] + b1;
            if (GELU) {
                v0 = 0.5f * v0 * (1.0f + erff(v0 * 0.70710678118654752f));
                v1 = 0.5f * v1 * (1.0f + erff(v1 * 0.70710678118654752f));
                v2 = 0.5f * v2 * (1.0f + erff(v2 * 0.70710678118654752f));
                v3 = 0.5f * v3 * (1.0f + erff(v3 * 0.70710678118654752f));
            }
            if (OUTH) {
                *(__half2*)(Ch + (size_t)r0 * N + c)       = __floats2half2_rn(v0, v1);
                *(__half2*)(Ch + (size_t)(r0 + 8) * N + c) = __floats2half2_rn(v2, v3);
            } else {
                *(float2*)(Cf + (size_t)r0 * N + c)       = make_float2(v0, v1);
                *(float2*)(Cf + (size_t)(r0 + 8) * N + c) = make_float2(v2, v3);
            }
        }
    }
}

// ---------------- fp16 tensor-core flash attention --------------------------
// grid (SS/128, NH, BB), 256 threads (8 warps x 16 q-rows), m16n8k16 f16 mma.
// SMEM (halfs): Q [128][72], K[2][64][72], V[2][64][72]  -> 55296 B
#define HP 72
#define AQ_OFF 0
#define AK_OFF (128 * HP)
#define AV_OFF (128 * HP + 2 * 64 * HP)
#define ATTN_SMEM_BYTES ((128 * HP + 4 * 64 * HP) * 2)

__global__ void __launch_bounds__(256)
attn_mma(const __half* __restrict__ qkvh, __half* __restrict__ ctxh)
{
    extern __shared__ __half hsm[];
    __half* sQ = hsm + AQ_OFF;
    const uint32_t sb = smem_u32(hsm);

    const int tid  = threadIdx.x;
    const int warp = tid >> 5;
    const int lane = tid & 31;
    const int g    = lane >> 2;
    const int t    = lane & 3;
    const int m0   = warp * 16;
    const int l16  = lane & 15;

    const int q0 = blockIdx.x * 128;
    const int h  = blockIdx.y;
    const int b  = blockIdx.z;

    const __half* Qg = qkvh + ((size_t)(b * SS) + q0) * H3 + h * HD;
    const __half* Kg = qkvh + (size_t)(b * SS) * H3 + HS     + h * HD;
    const __half* Vg = qkvh + (size_t)(b * SS) * H3 + 2 * HS + h * HD;

    // stage Q (128 x 64 halfs)
#pragma unroll
    for (int it = 0; it < 4; it++) {
        int item = tid + it * 256;
        int r = item >> 3, c = item & 7;
        *(uint4*)(sQ + r * HP + c * 8) = *(const uint4*)(Qg + (size_t)r * H3 + c * 8);
    }

    // issue K/V tile 0 via cp.async (buffer 0)
    {
        const uint32_t ka = sb + AK_OFF * 2;
        const uint32_t va = sb + AV_OFF * 2;
#pragma unroll
        for (int it = 0; it < 2; it++) {
            int item = tid + it * 256;
            int j = item >> 3, c = item & 7;
            const size_t go = (size_t)j * H3 + c * 8;
            cp16(ka + (j * HP + c * 8) * 2, Kg + go);
            cp16(va + (j * HP + c * 8) * 2, Vg + go);
        }
        cp_commit();
    }
    __syncthreads();   // Q visible

    // Q fragments, register resident: 4 k16-blocks x 4 regs
    uint32_t qf[4][4];
#pragma unroll
    for (int kb = 0; kb < 4; kb++) {
        qf[kb][0] = *(const uint32_t*)(sQ + (m0 + g)     * HP + kb * 16 + 2 * t);
        qf[kb][1] = *(const uint32_t*)(sQ + (m0 + g + 8) * HP + kb * 16 + 2 * t);
        qf[kb][2] = *(const uint32_t*)(sQ + (m0 + g)     * HP + kb * 16 + 8 + 2 * t);
        qf[kb][3] = *(const uint32_t*)(sQ + (m0 + g + 8) * HP + kb * 16 + 8 + 2 * t);
    }

    float mrow0 = -1e30f, mrow1 = -1e30f;
    float lrow0 = 0.f,    lrow1 = 0.f;
    float o[8][4];
#pragma unroll
    for (int ni = 0; ni < 8; ni++)
#pragma unroll
        for (int q = 0; q < 4; q++) o[ni][q] = 0.f;

    const float scale = 0.125f;
    const int NT = SS / 64;

    for (int kt = 0; kt < NT; kt++) {
        cp_wait<0>();
        __syncthreads();   // tile kt ready; all threads done with buf kt&1's previous use

        const int buf = kt & 1;
        const __half* sK = hsm + AK_OFF + buf * 64 * HP;
        const __half* sV = hsm + AV_OFF + buf * 64 * HP;
        const uint32_t svb = sb + (AV_OFF + buf * 64 * HP) * 2;

        if (kt + 1 < NT) {
            const int nb = buf ^ 1;
            const uint32_t ka = sb + (AK_OFF + nb * 64 * HP) * 2;
            const uint32_t va = sb + (AV_OFF + nb * 64 * HP) * 2;
#pragma unroll
            for (int it = 0; it < 2; it++) {
                int item = tid + it * 256;
                int j = item >> 3, c = item & 7;
                const size_t go = (size_t)((kt + 1) * 64 + j) * H3 + c * 8;
                cp16(ka + (j * HP + c * 8) * 2, Kg + go);
                cp16(va + (j * HP + c * 8) * 2, Vg + go);
            }
            cp_commit();
        }

        // S = Q @ K^T   (8 ni-blocks of 8 cols)
        float s_[8][4];
#pragma unroll
        for (int ni = 0; ni < 8; ni++)
#pragma unroll
            for (int q = 0; q < 4; q++) s_[ni][q] = 0.f;

#pragma unroll
        for (int kb = 0; kb < 4; kb++) {
#pragma unroll
            for (int ni = 0; ni < 8; ni++) {
                uint32_t bf[2];
                bf[0] = *(const uint32_t*)(sK + (ni * 8 + g) * HP + kb * 16 + 2 * t);
                bf[1] = *(const uint32_t*)(sK + (ni * 8 + g) * HP + kb * 16 + 8 + 2 * t);
                mma_f16(s_[ni], qf[kb], bf);
            }
        }

        // online softmax
        float mn0 = -1e30f, mn1 = -1e30f;
#pragma unroll
        for (int ni = 0; ni < 8; ni++) {
            s_[ni][0] *= scale; s_[ni][1] *= scale;
            s_[ni][2] *= scale; s_[ni][3] *= scale;
            mn0 = fmaxf(mn0, fmaxf(s_[ni][0], s_[ni][1]));
            mn1 = fmaxf(mn1, fmaxf(s_[ni][2], s_[ni][3]));
        }
        mn0 = fmaxf(mn0, __shfl_xor_sync(0xffffffffu, mn0, 1));
        mn0 = fmaxf(mn0, __shfl_xor_sync(0xffffffffu, mn0, 2));
        mn1 = fmaxf(mn1, __shfl_xor_sync(0xffffffffu, mn1, 1));
        mn1 = fmaxf(mn1, __shfl_xor_sync(0xffffffffu, mn1, 2));

        const float mnew0 = fmaxf(mrow0, mn0);
        const float mnew1 = fmaxf(mrow1, mn1);
        const float a0 = __expf(mrow0 - mnew0);
        const float a1 = __expf(mrow1 - mnew1);
        mrow0 = mnew0; mrow1 = mnew1;

        float ladd0 = 0.f, ladd1 = 0.f;
#pragma unroll
        for (int ni = 0; ni < 8; ni++) {
            s_[ni][0] = __expf(s_[ni][0] - mnew0);
            s_[ni][1] = __expf(s_[ni][1] - mnew0);
            s_[ni][2] = __expf(s_[ni][2] - mnew1);
            s_[ni][3] = __expf(s_[ni][3] - mnew1);
            ladd0 += s_[ni][0] + s_[ni][1];
            ladd1 += s_[ni][2] + s_[ni][3];
            o[ni][0] *= a0; o[ni][1] *= a0;
            o[ni][2] *= a1; o[ni][3] *= a1;
        }
        ladd0 += __shfl_xor_sync(0xffffffffu, ladd0, 1);
        ladd0 += __shfl_xor_sync(0xffffffffu, ladd0, 2);
        ladd1 += __shfl_xor_sync(0xffffffffu, ladd1, 1);
        ladd1 += __shfl_xor_sync(0xffffffffu, ladd1, 2);
        lrow0 = lrow0 * a0 + ladd0;
        lrow1 = lrow1 * a1 + ladd1;

        // O += P @ V : P fragments packed directly from s_ registers.
#pragma unroll
        for (int kb = 0; kb < 4; kb++) {
            uint32_t af[4];
            {
                __half2 h0 = __floats2half2_rn(s_[2 * kb][0],     s_[2 * kb][1]);
                __half2 h1 = __floats2half2_rn(s_[2 * kb][2],     s_[2 * kb][3]);
                __half2 h2 = __floats2half2_rn(s_[2 * kb + 1][0], s_[2 * kb + 1][1]);
                __half2 h3 = __floats2half2_rn(s_[2 * kb + 1][2], s_[2 * kb + 1][3]);
                af[0] = *(uint32_t*)&h0;
                af[1] = *(uint32_t*)&h1;
                af[2] = *(uint32_t*)&h2;
                af[3] = *(uint32_t*)&h3;
            }
            const uint32_t rowaddr = svb + ((kb * 16 + l16) * HP) * 2;
#pragma unroll
            for (int ni = 0; ni < 8; ni++) {
                uint32_t bf0, bf1;
                ldmx2t(bf0, bf1, rowaddr + ni * 16);
                uint32_t bf[2] = { bf0, bf1 };
                mma_f16(o[ni], af, bf);
            }
        }
    }

    const float inv0 = 1.0f / lrow0;
    const float inv1 = 1.0f / lrow1;
    const int qr0 = q0 + m0 + g;
    __half* dst0 = ctxh + ((size_t)(b * SS) + qr0)     * HS + h * HD;
    __half* dst1 = ctxh + ((size_t)(b * SS) + qr0 + 8) * HS + h * HD;
#pragma unroll
    for (int ni = 0; ni < 8; ni++) {
        const int c = ni * 8 + 2 * t;
        *(__half2*)(dst0 + c) = __floats2half2_rn(o[ni][0] * inv0, o[ni][1] * inv0);
        *(__half2*)(dst1 + c) = __floats2half2_rn(o[ni][2] * inv1, o[ni][3] * inv1);
    }
}

// ---------------- residual add + LayerNorm --------------------------------
template<int WH>
__global__ void __launch_bounds__(256)
addln_kernel(const float* __restrict__ a, const float* __restrict__ res,
             const float* __restrict__ g, const float* __restrict__ bb,
             float* __restrict__ outf, __half* __restrict__ outh)
{
    __shared__ float wsum[8], wsq[8];
    __shared__ float s_mu, s_rstd;

    const int row = blockIdx.x;
    const int tid = threadIdx.x;
    const float* ar = a   + (size_t)row * HS;
    const float* rr = res + (size_t)row * HS;

    float v[3];
    float sum = 0.f, sq = 0.f;
#pragma unroll
    for (int i = 0; i < 3; i++) {
        int idx = tid + i * 256;
        v[i] = ar[idx] + rr[idx];
        sum += v[i];
        sq  += v[i] * v[i];
    }
#pragma unroll
    for (int off = 16; off > 0; off >>= 1) {
        sum += __shfl_down_sync(0xffffffffu, sum, off);
        sq  += __shfl_down_sync(0xffffffffu, sq,  off);
    }
    if ((tid & 31) == 0) { wsum[tid >> 5] = sum; wsq[tid >> 5] = sq; }
    __syncthreads();
    if (tid == 0) {
        float s = 0.f, q = 0.f;
#pragma unroll
        for (int i = 0; i < 8; i++) { s += wsum[i]; q += wsq[i]; }
        float mu  = s * (1.f / HS);
        float var = q * (1.f / HS) - mu * mu;
        s_mu = mu;
        s_rstd = rsqrtf(fmaxf(var, 0.f) + 1e-12f);
    }
    __syncthreads();
    float mu = s_mu, rstd = s_rstd;
#pragma unroll
    for (int i = 0; i < 3; i++) {
        int idx = tid + i * 256;
        float r = (v[i] - mu) * rstd * g[idx] + bb[idx];
        outf[(size_t)row * HS + idx] = r;
        if (WH) outh[(size_t)row * HS + idx] = __float2half_rn(r);
    }
}

// ---------------- launch ---------------------------------------------------
extern "C" void kernel_launch(void* const* d_in, const int* in_sizes, int n_in,
                              void* d_out, int out_size)
{
    const float* x     = (const float*)d_in[0];
    const float* w_qkv = (const float*)d_in[1];
    const float* b_qkv = (const float*)d_in[2];
    const float* w_out = (const float*)d_in[3];
    const float* b_out = (const float*)d_in[4];
    const float* w_ff1 = (const float*)d_in[5];
    const float* b_ff1 = (const float*)d_in[6];
    const float* w_ff2 = (const float*)d_in[7];
    const float* b_ff2 = (const float*)d_in[8];
    const float* g1    = (const float*)d_in[9];
    const float* be1   = (const float*)d_in[10];
    const float* g2    = (const float*)d_in[11];
    const float* be2   = (const float*)d_in[12];
    float* out = (float*)d_out;

    __half *xh, *wqkvT, *woutT, *wff1T, *wff2T, *qkvh, *ctxh, *x1h, *h1h;
    float *ao, *x1, *f2;
    cudaGetSymbolAddress((void**)&xh,    g_xh);
    cudaGetSymbolAddress((void**)&wqkvT, g_wqkvT);
    cudaGetSymbolAddress((void**)&woutT, g_woutT);
    cudaGetSymbolAddress((void**)&wff1T, g_wff1T);
    cudaGetSymbolAddress((void**)&wff2T, g_wff2T);
    cudaGetSymbolAddress((void**)&qkvh,  g_qkvh);
    cudaGetSymbolAddress((void**)&ctxh,  g_ctxh);
    cudaGetSymbolAddress((void**)&x1h,   g_x1h);
    cudaGetSymbolAddress((void**)&h1h,   g_h1h);
    cudaGetSymbolAddress((void**)&ao,    g_ao);
    cudaGetSymbolAddress((void**)&x1,    g_x1);
    cudaGetSymbolAddress((void**)&f2,    g_f2);

    cudaFuncSetAttribute(attn_mma,
                         cudaFuncAttributeMaxDynamicSharedMemorySize, ATTN_SMEM_BYTES);
    cudaFuncSetAttribute(gemm_h<0,0>, cudaFuncAttributeMaxDynamicSharedMemorySize, GH_SMEM_BYTES);
    cudaFuncSetAttribute(gemm_h<0,1>, cudaFuncAttributeMaxDynamicSharedMemorySize, GH_SMEM_BYTES);
    cudaFuncSetAttribute(gemm_h<1,1>, cudaFuncAttributeMaxDynamicSharedMemorySize, GH_SMEM_BYTES);

    dim3 tb(32, 8);

    f2h_kernel<<<(MM * HS / 4 + 255) / 256, 256>>>(x, xh, MM * HS / 4);
    transpose_h<<<dim3(H3 / 32, HS / 32), tb>>>(w_qkv, wqkvT, HS, H3);
    transpose_h<<<dim3(HS / 32, HS / 32), tb>>>(w_out, woutT, HS, HS);
    transpose_h<<<dim3(FF / 32, HS / 32), tb>>>(w_ff1, wff1T, HS, FF);
    transpose_h<<<dim3(HS / 32, FF / 32), tb>>>(w_ff2, wff2T, FF, HS);

    // 1) QKV projection -> fp16 qkv
    gemm_h<0,1><<<dim3(H3 / 128, MM / 128), 256, GH_SMEM_BYTES>>>(
        xh, wqkvT, b_qkv, nullptr, qkvh, H3, HS);

    // 2) fp16 flash attention -> fp16 ctx
    attn_mma<<<dim3(SS / 128, NH, BB), 256, ATTN_SMEM_BYTES>>>(qkvh, ctxh);

    // 3) output projection -> fp32 ao
    gemm_h<0,0><<<dim3(HS / 128, MM / 128), 256, GH_SMEM_BYTES>>>(
        ctxh, woutT, b_out, ao, nullptr, HS, HS);

    // 4) x1 = LN(x + ao), dual write fp32 + fp16
    addln_kernel<1><<<MM, 256>>>(ao, x, g1, be1, x1, x1h);

    // 5) h1 = gelu(x1 @ w_ff1 + b_ff1) -> fp16
    gemm_h<1,1><<<dim3(FF / 128, MM / 128), 256, GH_SMEM_BYTES>>>(
        x1h, wff1T, b_ff1, nullptr, h1h, FF, HS);

    // 6) f2 = h1 @ w_ff2 + b_ff2 -> fp32
    gemm_h<0,0><<<dim3(HS / 128, MM / 128), 256, GH_SMEM_BYTES>>>(
        h1h, wff2T, b_ff2, f2, nullptr, HS, FF);

    // 7) out = LN(x1 + f2)
    addln_kernel<0><<<MM, 256>>>(f2, x1, g2, be2, out, nullptr);
}

// round 7
// speedup vs baseline: 6.5340x; 1.0709x over previous
#include <cuda_runtime.h>
#include <cuda_fp16.h>
#include <math.h>
#include <stdint.h>

#define HS   768
#define NH   12
#define HD   64
#define FF   3072
#define BB   4
#define SS   2048
#define MM   (BB*SS)     /* 8192 rows */
#define H3   (3*HS)      /* 2304 */

// ---------------- scratch (device globals, no allocation) ----------------
__device__ __half g_xh   [(size_t)MM * HS];
__device__ __half g_wqkvT[(size_t)H3 * HS];
__device__ __half g_woutT[(size_t)HS * HS];
__device__ __half g_wff1T[(size_t)FF * HS];
__device__ __half g_wff2T[(size_t)HS * FF];
__device__ __half g_qkvh [(size_t)MM * H3];
__device__ __half g_ctxh [(size_t)MM * HS];
__device__ float  g_ao   [(size_t)MM * HS];
__device__ float  g_x1   [(size_t)MM * HS];
__device__ __half g_x1h  [(size_t)MM * HS];
__device__ __half g_h1h  [(size_t)MM * FF];
__device__ float  g_f2   [(size_t)MM * HS];

// ================= helpers ==================================================
__device__ __forceinline__ uint32_t smem_u32(const void* p) {
    uint32_t a;
    asm("{ .reg .u64 t; cvta.to.shared.u64 t, %1; cvt.u32.u64 %0, t; }" : "=r"(a) : "l"(p));
    return a;
}
__device__ __forceinline__ void cp16(uint32_t s, const void* g) {
    asm volatile("cp.async.cg.shared.global [%0], [%1], 16;" :: "r"(s), "l"(g) : "memory");
}
__device__ __forceinline__ void cp_commit() {
    asm volatile("cp.async.commit_group;" ::: "memory");
}
template<int N> __device__ __forceinline__ void cp_wait() {
    asm volatile("cp.async.wait_group %0;" :: "n"(N) : "memory");
}
__device__ __forceinline__ void mma_f16(float c[4], const uint32_t a[4], const uint32_t b[2]) {
    asm volatile(
        "mma.sync.aligned.m16n8k16.row.col.f32.f16.f16.f32 "
        "{%0,%1,%2,%3}, {%4,%5,%6,%7}, {%8,%9}, {%0,%1,%2,%3};"
        : "+f"(c[0]), "+f"(c[1]), "+f"(c[2]), "+f"(c[3])
        : "r"(a[0]), "r"(a[1]), "r"(a[2]), "r"(a[3]), "r"(b[0]), "r"(b[1]));
}
__device__ __forceinline__ void ldmx4(uint32_t r[4], uint32_t addr) {
    asm volatile("ldmatrix.sync.aligned.m8n8.x4.shared.b16 {%0,%1,%2,%3}, [%4];"
                 : "=r"(r[0]), "=r"(r[1]), "=r"(r[2]), "=r"(r[3]) : "r"(addr));
}
__device__ __forceinline__ void ldmx2t(uint32_t& b0, uint32_t& b1, uint32_t addr) {
    asm volatile("ldmatrix.sync.aligned.m8n8.x2.trans.shared.b16 {%0,%1}, [%2];"
                 : "=r"(b0), "=r"(b1) : "r"(addr));
}

// ---------------- pre-pass: fp32 -> fp16 ----------------------------------
__global__ void __launch_bounds__(256)
f2h_kernel(const float* __restrict__ in, __half* __restrict__ out, int n4)
{
    int i = blockIdx.x * 256 + threadIdx.x;
    if (i < n4) {
        float4 v = *(const float4*)(in + (size_t)i * 4);
        __half2 h0 = __floats2half2_rn(v.x, v.y);
        __half2 h1 = __floats2half2_rn(v.z, v.w);
        *(uint2*)(out + (size_t)i * 4) = make_uint2(*(uint32_t*)&h0, *(uint32_t*)&h1);
    }
}

// W[K][N] fp32 -> WT[N][K] fp16.  grid (N/32, K/32), block (32,8)
__global__ void __launch_bounds__(256)
transpose_h(const float* __restrict__ W, __half* __restrict__ WT, int K, int N)
{
    __shared__ float t[32][33];
    const int n0 = blockIdx.x * 32, k0 = blockIdx.y * 32;
    const int tx = threadIdx.x, ty = threadIdx.y;
#pragma unroll
    for (int i = 0; i < 4; i++)
        t[ty + i * 8][tx] = W[(size_t)(k0 + ty + i * 8) * N + n0 + tx];
    __syncthreads();
#pragma unroll
    for (int i = 0; i < 4; i++)
        WT[(size_t)(n0 + ty + i * 8) * K + k0 + tx] = __float2half_rn(t[tx][ty + i * 8]);
}

// ---------------- fp16 mma GEMM, ldmatrix fragments ------------------------
#define PITCH  40
#define AST    (128 * PITCH)
#define STG_H  (2 * AST)
#define STAGES 4
#define GH_SMEM_BYTES (STAGES * STG_H * 2)

template<int GELU, int OUTH>
__global__ void __launch_bounds__(256, 2)
gemm_h(const __half* __restrict__ A, const __half* __restrict__ WT,
       const float* __restrict__ bias,
       float* __restrict__ Cf, __half* __restrict__ Ch,
       int N, int K)
{
    extern __shared__ __half hsm[];
    const uint32_t sbase = smem_u32(hsm);

    const int tid  = threadIdx.x;
    const int warp = tid >> 5;
    const int lane = tid & 31;
    const int g    = lane >> 2;
    const int t    = lane & 3;
    const int wm   = warp >> 2;
    const int wn   = warp & 3;
    const int row0 = blockIdx.y * 128;
    const int col0 = blockIdx.x * 128;
    const int KT   = K >> 5;

    const __half* Ab = A  + (size_t)row0 * K;
    const __half* Bb = WT + (size_t)col0 * K;

    const int cr = tid >> 2;
    const int cc = tid & 3;

    // ldmatrix lane-address components (in half units, added to kb/base later)
    const int lm_arow = wm * 64 + (lane & 15);              // + mi*16
    const int lm_acol = (lane >> 4) * 8;
    const int lm_brow = wn * 32 + (lane & 7) + ((lane >> 4) << 3);  // + nip*16
    const int lm_bcol = ((lane >> 3) & 1) * 8;

    float acc[4][4][4];
#pragma unroll
    for (int mi = 0; mi < 4; mi++)
#pragma unroll
        for (int ni = 0; ni < 4; ni++)
#pragma unroll
            for (int q = 0; q < 4; q++) acc[mi][ni][q] = 0.f;

#pragma unroll
    for (int s = 0; s < 3; s++) {
        const uint32_t sa = sbase + s * STG_H * 2;
        const int k0 = s * 32;
#pragma unroll
        for (int j = 0; j < 2; j++) {
            int r = cr + j * 64;
            cp16(sa + (r * PITCH + cc * 8) * 2,       Ab + (size_t)r * K + k0 + cc * 8);
            cp16(sa + (AST + r * PITCH + cc * 8) * 2, Bb + (size_t)r * K + k0 + cc * 8);
        }
        cp_commit();
    }

    for (int it = 0; it < KT; it++) {
        if (it + 2 < KT)      cp_wait<2>();
        else if (it + 1 < KT) cp_wait<1>();
        else                  cp_wait<0>();
        __syncthreads();

        if (it + 3 < KT) {
            const int s = (it + 3) & 3;
            const uint32_t sa = sbase + s * STG_H * 2;
            const int k0 = (it + 3) * 32;
#pragma unroll
            for (int j = 0; j < 2; j++) {
                int r = cr + j * 64;
                cp16(sa + (r * PITCH + cc * 8) * 2,       Ab + (size_t)r * K + k0 + cc * 8);
                cp16(sa + (AST + r * PITCH + cc * 8) * 2, Bb + (size_t)r * K + k0 + cc * 8);
            }
            cp_commit();
        }

        const uint32_t cAu = sbase + (uint32_t)((it & 3) * STG_H) * 2;
        const uint32_t cBu = cAu + AST * 2;
#pragma unroll
        for (int ks = 0; ks < 2; ks++) {
            const int kb = ks * 16;
            uint32_t af[4][4], bf[4][2];
#pragma unroll
            for (int mi = 0; mi < 4; mi++)
                ldmx4(af[mi], cAu + (((lm_arow + mi * 16) * PITCH) + kb + lm_acol) * 2);
#pragma unroll
            for (int nip = 0; nip < 2; nip++) {
                uint32_t r[4];
                ldmx4(r, cBu + (((lm_brow + nip * 16) * PITCH) + kb + lm_bcol) * 2);
                bf[nip * 2][0]     = r[0];
                bf[nip * 2][1]     = r[1];
                bf[nip * 2 + 1][0] = r[2];
                bf[nip * 2 + 1][1] = r[3];
            }
#pragma unroll
            for (int mi = 0; mi < 4; mi++)
#pragma unroll
                for (int ni = 0; ni < 4; ni++)
                    mma_f16(acc[mi][ni], af[mi], bf[ni]);
        }
    }

#pragma unroll
    for (int mi = 0; mi < 4; mi++) {
        const int r0 = row0 + wm * 64 + mi * 16 + g;
#pragma unroll
        for (int ni = 0; ni < 4; ni++) {
            const int c = col0 + wn * 32 + ni * 8 + 2 * t;
            const float b0 = __ldg(bias + c);
            const float b1 = __ldg(bias + c + 1);
            float v0 = acc[mi][ni][0] + b0;
            float v1 = acc[mi][ni][1] + b1;
            float v2 = acc[mi][ni][2] + b0;
            float v3 = acc[mi][ni][3] + b1;
            if (GELU) {
                v0 = 0.5f * v0 * (1.0f + erff(v0 * 0.70710678118654752f));
                v1 = 0.5f * v1 * (1.0f + erff(v1 * 0.70710678118654752f));
                v2 = 0.5f * v2 * (1.0f + erff(v2 * 0.70710678118654752f));
                v3 = 0.5f * v3 * (1.0f + erff(v3 * 0.70710678118654752f));
            }
            if (OUTH) {
                *(__half2*)(Ch + (size_t)r0 * N + c)       = __floats2half2_rn(v0, v1);
                *(__half2*)(Ch + (size_t)(r0 + 8) * N + c) = __floats2half2_rn(v2, v3);
            } else {
                *(float2*)(Cf + (size_t)r0 * N + c)       = make_float2(v0, v1);
                *(float2*)(Cf + (size_t)(r0 + 8) * N + c) = make_float2(v2, v3);
            }
        }
    }
}

// ---------------- fp16 tensor-core flash attention --------------------------
// grid (SS/128, NH, BB), 256 threads (8 warps x 16 q-rows), m16n8k16 f16 mma.
#define HP 72
#define AQ_OFF 0
#define AK_OFF (128 * HP)
#define AV_OFF (128 * HP + 2 * 64 * HP)
#define ATTN_SMEM_BYTES ((128 * HP + 4 * 64 * HP) * 2)

__global__ void __launch_bounds__(256)
attn_mma(const __half* __restrict__ qkvh, __half* __restrict__ ctxh)
{
    extern __shared__ __half hsm[];
    __half* sQ = hsm + AQ_OFF;
    const uint32_t sb = smem_u32(hsm);

    const int tid  = threadIdx.x;
    const int warp = tid >> 5;
    const int lane = tid & 31;
    const int g    = lane >> 2;
    const int t    = lane & 3;
    const int m0   = warp * 16;
    const int l16  = lane & 15;

    const int q0 = blockIdx.x * 128;
    const int h  = blockIdx.y;
    const int b  = blockIdx.z;

    const __half* Qg = qkvh + ((size_t)(b * SS) + q0) * H3 + h * HD;
    const __half* Kg = qkvh + (size_t)(b * SS) * H3 + HS     + h * HD;
    const __half* Vg = qkvh + (size_t)(b * SS) * H3 + 2 * HS + h * HD;

    // K-fragment ldmatrix lane components
    const int lm_krow = (lane & 7) + ((lane >> 4) << 3);   // + nip*16
    const int lm_kcol = ((lane >> 3) & 1) * 8;

    // stage Q (128 x 64 halfs)
#pragma unroll
    for (int it = 0; it < 4; it++) {
        int item = tid + it * 256;
        int r = item >> 3, c = item & 7;
        *(uint4*)(sQ + r * HP + c * 8) = *(const uint4*)(Qg + (size_t)r * H3 + c * 8);
    }

    // issue K/V tile 0 via cp.async (buffer 0)
    {
        const uint32_t ka = sb + AK_OFF * 2;
        const uint32_t va = sb + AV_OFF * 2;
#pragma unroll
        for (int it = 0; it < 2; it++) {
            int item = tid + it * 256;
            int j = item >> 3, c = item & 7;
            const size_t go = (size_t)j * H3 + c * 8;
            cp16(ka + (j * HP + c * 8) * 2, Kg + go);
            cp16(va + (j * HP + c * 8) * 2, Vg + go);
        }
        cp_commit();
    }
    __syncthreads();   // Q visible

    uint32_t qf[4][4];
#pragma unroll
    for (int kb = 0; kb < 4; kb++) {
        qf[kb][0] = *(const uint32_t*)(sQ + (m0 + g)     * HP + kb * 16 + 2 * t);
        qf[kb][1] = *(const uint32_t*)(sQ + (m0 + g + 8) * HP + kb * 16 + 2 * t);
        qf[kb][2] = *(const uint32_t*)(sQ + (m0 + g)     * HP + kb * 16 + 8 + 2 * t);
        qf[kb][3] = *(const uint32_t*)(sQ + (m0 + g + 8) * HP + kb * 16 + 8 + 2 * t);
    }

    float mrow0 = -1e30f, mrow1 = -1e30f;
    float lrow0 = 0.f,    lrow1 = 0.f;
    float o[8][4];
#pragma unroll
    for (int ni = 0; ni < 8; ni++)
#pragma unroll
        for (int q = 0; q < 4; q++) o[ni][q] = 0.f;

    const float scale = 0.125f;
    const int NT = SS / 64;

    for (int kt = 0; kt < NT; kt++) {
        cp_wait<0>();
        __syncthreads();

        const int buf = kt & 1;
        const uint32_t skb = sb + (AK_OFF + buf * 64 * HP) * 2;
        const uint32_t svb = sb + (AV_OFF + buf * 64 * HP) * 2;

        if (kt + 1 < NT) {
            const int nb = buf ^ 1;
            const uint32_t ka = sb + (AK_OFF + nb * 64 * HP) * 2;
            const uint32_t va = sb + (AV_OFF + nb * 64 * HP) * 2;
#pragma unroll
            for (int it = 0; it < 2; it++) {
                int item = tid + it * 256;
                int j = item >> 3, c = item & 7;
                const size_t go = (size_t)((kt + 1) * 64 + j) * H3 + c * 8;
                cp16(ka + (j * HP + c * 8) * 2, Kg + go);
                cp16(va + (j * HP + c * 8) * 2, Vg + go);
            }
            cp_commit();
        }

        // S = Q @ K^T via ldmatrix.x4 K fragments
        float s_[8][4];
#pragma unroll
        for (int ni = 0; ni < 8; ni++)
#pragma unroll
            for (int q = 0; q < 4; q++) s_[ni][q] = 0.f;

#pragma unroll
        for (int kb = 0; kb < 4; kb++) {
#pragma unroll
            for (int nip = 0; nip < 4; nip++) {
                uint32_t r[4];
                ldmx4(r, skb + (((nip * 16 + lm_krow) * HP) + kb * 16 + lm_kcol) * 2);
                uint32_t bf0[2] = { r[0], r[1] };
                uint32_t bf1[2] = { r[2], r[3] };
                mma_f16(s_[nip * 2],     qf[kb], bf0);
                mma_f16(s_[nip * 2 + 1], qf[kb], bf1);
            }
        }

        // online softmax
        float mn0 = -1e30f, mn1 = -1e30f;
#pragma unroll
        for (int ni = 0; ni < 8; ni++) {
            s_[ni][0] *= scale; s_[ni][1] *= scale;
            s_[ni][2] *= scale; s_[ni][3] *= scale;
            mn0 = fmaxf(mn0, fmaxf(s_[ni][0], s_[ni][1]));
            mn1 = fmaxf(mn1, fmaxf(s_[ni][2], s_[ni][3]));
        }
        mn0 = fmaxf(mn0, __shfl_xor_sync(0xffffffffu, mn0, 1));
        mn0 = fmaxf(mn0, __shfl_xor_sync(0xffffffffu, mn0, 2));
        mn1 = fmaxf(mn1, __shfl_xor_sync(0xffffffffu, mn1, 1));
        mn1 = fmaxf(mn1, __shfl_xor_sync(0xffffffffu, mn1, 2));

        const float mnew0 = fmaxf(mrow0, mn0);
        const float mnew1 = fmaxf(mrow1, mn1);
        const float a0 = __expf(mrow0 - mnew0);
        const float a1 = __expf(mrow1 - mnew1);
        mrow0 = mnew0; mrow1 = mnew1;

        float ladd0 = 0.f, ladd1 = 0.f;
#pragma unroll
        for (int ni = 0; ni < 8; ni++) {
            s_[ni][0] = __expf(s_[ni][0] - mnew0);
            s_[ni][1] = __expf(s_[ni][1] - mnew0);
            s_[ni][2] = __expf(s_[ni][2] - mnew1);
            s_[ni][3] = __expf(s_[ni][3] - mnew1);
            ladd0 += s_[ni][0] + s_[ni][1];
            ladd1 += s_[ni][2] + s_[ni][3];
            o[ni][0] *= a0; o[ni][1] *= a0;
            o[ni][2] *= a1; o[ni][3] *= a1;
        }
        ladd0 += __shfl_xor_sync(0xffffffffu, ladd0, 1);
        ladd0 += __shfl_xor_sync(0xffffffffu, ladd0, 2);
        ladd1 += __shfl_xor_sync(0xffffffffu, ladd1, 1);
        ladd1 += __shfl_xor_sync(0xffffffffu, ladd1, 2);
        lrow0 = lrow0 * a0 + ladd0;
        lrow1 = lrow1 * a1 + ladd1;

        // O += P @ V : P fragments packed directly from registers.
#pragma unroll
        for (int kb = 0; kb < 4; kb++) {
            uint32_t af[4];
            {
                __half2 h0 = __floats2half2_rn(s_[2 * kb][0],     s_[2 * kb][1]);
                __half2 h1 = __floats2half2_rn(s_[2 * kb][2],     s_[2 * kb][3]);
                __half2 h2 = __floats2half2_rn(s_[2 * kb + 1][0], s_[2 * kb + 1][1]);
                __half2 h3 = __floats2half2_rn(s_[2 * kb + 1][2], s_[2 * kb + 1][3]);
                af[0] = *(uint32_t*)&h0;
                af[1] = *(uint32_t*)&h1;
                af[2] = *(uint32_t*)&h2;
                af[3] = *(uint32_t*)&h3;
            }
            const uint32_t rowaddr = svb + ((kb * 16 + l16) * HP) * 2;
#pragma unroll
            for (int ni = 0; ni < 8; ni++) {
                uint32_t bf0, bf1;
                ldmx2t(bf0, bf1, rowaddr + ni * 16);
                uint32_t bf[2] = { bf0, bf1 };
                mma_f16(o[ni], af, bf);
            }
        }
    }

    const float inv0 = 1.0f / lrow0;
    const float inv1 = 1.0f / lrow1;
    const int qr0 = q0 + m0 + g;
    __half* dst0 = ctxh + ((size_t)(b * SS) + qr0)     * HS + h * HD;
    __half* dst1 = ctxh + ((size_t)(b * SS) + qr0 + 8) * HS + h * HD;
#pragma unroll
    for (int ni = 0; ni < 8; ni++) {
        const int c = ni * 8 + 2 * t;
        *(__half2*)(dst0 + c) = __floats2half2_rn(o[ni][0] * inv0, o[ni][1] * inv0);
        *(__half2*)(dst1 + c) = __floats2half2_rn(o[ni][2] * inv1, o[ni][3] * inv1);
    }
}

// ---------------- residual add + LayerNorm --------------------------------
template<int WH>
__global__ void __launch_bounds__(256)
addln_kernel(const float* __restrict__ a, const float* __restrict__ res,
             const float* __restrict__ g, const float* __restrict__ bb,
             float* __restrict__ outf, __half* __restrict__ outh)
{
    __shared__ float wsum[8], wsq[8];
    __shared__ float s_mu, s_rstd;

    const int row = blockIdx.x;
    const int tid = threadIdx.x;
    const float* ar = a   + (size_t)row * HS;
    const float* rr = res + (size_t)row * HS;

    float v[3];
    float sum = 0.f, sq = 0.f;
#pragma unroll
    for (int i = 0; i < 3; i++) {
        int idx = tid + i * 256;
        v[i] = ar[idx] + rr[idx];
        sum += v[i];
        sq  += v[i] * v[i];
    }
#pragma unroll
    for (int off = 16; off > 0; off >>= 1) {
        sum += __shfl_down_sync(0xffffffffu, sum, off);
        sq  += __shfl_down_sync(0xffffffffu, sq,  off);
    }
    if ((tid & 31) == 0) { wsum[tid >> 5] = sum; wsq[tid >> 5] = sq; }
    __syncthreads();
    if (tid == 0) {
        float s = 0.f, q = 0.f;
#pragma unroll
        for (int i = 0; i < 8; i++) { s += wsum[i]; q += wsq[i]; }
        float mu  = s * (1.f / HS);
        float var = q * (1.f / HS) - mu * mu;
        s_mu = mu;
        s_rstd = rsqrtf(fmaxf(var, 0.f) + 1e-12f);
    }
    __syncthreads();
    float mu = s_mu, rstd = s_rstd;
#pragma unroll
    for (int i = 0; i < 3; i++) {
        int idx = tid + i * 256;
        float r = (v[i] - mu) * rstd * g[idx] + bb[idx];
        outf[(size_t)row * HS + idx] = r;
        if (WH) outh[(size_t)row * HS + idx] = __float2half_rn(r);
    }
}

// ---------------- launch ---------------------------------------------------
extern "C" void kernel_launch(void* const* d_in, const int* in_sizes, int n_in,
                              void* d_out, int out_size)
{
    const float* x     = (const float*)d_in[0];
    const float* w_qkv = (const float*)d_in[1];
    const float* b_qkv = (const float*)d_in[2];
    const float* w_out = (const float*)d_in[3];
    const float* b_out = (const float*)d_in[4];
    const float* w_ff1 = (const float*)d_in[5];
    const float* b_ff1 = (const float*)d_in[6];
    const float* w_ff2 = (const float*)d_in[7];
    const float* b_ff2 = (const float*)d_in[8];
    const float* g1    = (const float*)d_in[9];
    const float* be1   = (const float*)d_in[10];
    const float* g2    = (const float*)d_in[11];
    const float* be2   = (const float*)d_in[12];
    float* out = (float*)d_out;

    __half *xh, *wqkvT, *woutT, *wff1T, *wff2T, *qkvh, *ctxh, *x1h, *h1h;
    float *ao, *x1, *f2;
    cudaGetSymbolAddress((void**)&xh,    g_xh);
    cudaGetSymbolAddress((void**)&wqkvT, g_wqkvT);
    cudaGetSymbolAddress((void**)&woutT, g_woutT);
    cudaGetSymbolAddress((void**)&wff1T, g_wff1T);
    cudaGetSymbolAddress((void**)&wff2T, g_wff2T);
    cudaGetSymbolAddress((void**)&qkvh,  g_qkvh);
    cudaGetSymbolAddress((void**)&ctxh,  g_ctxh);
    cudaGetSymbolAddress((void**)&x1h,   g_x1h);
    cudaGetSymbolAddress((void**)&h1h,   g_h1h);
    cudaGetSymbolAddress((void**)&ao,    g_ao);
    cudaGetSymbolAddress((void**)&x1,    g_x1);
    cudaGetSymbolAddress((void**)&f2,    g_f2);

    cudaFuncSetAttribute(attn_mma,
                         cudaFuncAttributeMaxDynamicSharedMemorySize, ATTN_SMEM_BYTES);
    cudaFuncSetAttribute(gemm_h<0,0>, cudaFuncAttributeMaxDynamicSharedMemorySize, GH_SMEM_BYTES);
    cudaFuncSetAttribute(gemm_h<0,1>, cudaFuncAttributeMaxDynamicSharedMemorySize, GH_SMEM_BYTES);
    cudaFuncSetAttribute(gemm_h<1,1>, cudaFuncAttributeMaxDynamicSharedMemorySize, GH_SMEM_BYTES);

    dim3 tb(32, 8);

    f2h_kernel<<<(MM * HS / 4 + 255) / 256, 256>>>(x, xh, MM * HS / 4);
    transpose_h<<<dim3(H3 / 32, HS / 32), tb>>>(w_qkv, wqkvT, HS, H3);
    transpose_h<<<dim3(HS / 32, HS / 32), tb>>>(w_out, woutT, HS, HS);
    transpose_h<<<dim3(FF / 32, HS / 32), tb>>>(w_ff1, wff1T, HS, FF);
    transpose_h<<<dim3(HS / 32, FF / 32), tb>>>(w_ff2, wff2T, FF, HS);

    // 1) QKV projection -> fp16 qkv
    gemm_h<0,1><<<dim3(H3 / 128, MM / 128), 256, GH_SMEM_BYTES>>>(
        xh, wqkvT, b_qkv, nullptr, qkvh, H3, HS);

    // 2) fp16 flash attention -> fp16 ctx
    attn_mma<<<dim3(SS / 128, NH, BB), 256, ATTN_SMEM_BYTES>>>(qkvh, ctxh);

    // 3) output projection -> fp32 ao
    gemm_h<0,0><<<dim3(HS / 128, MM / 128), 256, GH_SMEM_BYTES>>>(
        ctxh, woutT, b_out, ao, nullptr, HS, HS);

    // 4) x1 = LN(x + ao), dual write fp32 + fp16
    addln_kernel<1><<<MM, 256>>>(ao, x, g1, be1, x1, x1h);

    // 5) h1 = gelu(x1 @ w_ff1 + b_ff1) -> fp16
    gemm_h<1,1><<<dim3(FF / 128, MM / 128), 256, GH_SMEM_BYTES>>>(
        x1h, wff1T, b_ff1, nullptr, h1h, FF, HS);

    // 6) f2 = h1 @ w_ff2 + b_ff2 -> fp32
    gemm_h<0,0><<<dim3(HS / 128, MM / 128), 256, GH_SMEM_BYTES>>>(
        h1h, wff2T, b_ff2, f2, nullptr, HS, FF);

    // 7) out = LN(x1 + f2)
    addln_kernel<0><<<MM, 256>>>(f2, x1, g2, be2, out, nullptr);
}

// round 8
// speedup vs baseline: 6.5720x; 1.0058x over previous
#include <cuda_runtime.h>
#include <cuda_fp16.h>
#include <math.h>
#include <stdint.h>

#define HS   768
#define NH   12
#define HD   64
#define FF   3072
#define BB   4
#define SS   2048
#define MM   (BB*SS)     /* 8192 rows */
#define H3   (3*HS)      /* 2304 */

// ---------------- scratch (device globals, no allocation) ----------------
__device__ __half g_xh   [(size_t)MM * HS];
__device__ __half g_wqkvT[(size_t)H3 * HS];
__device__ __half g_woutT[(size_t)HS * HS];
__device__ __half g_wff1T[(size_t)FF * HS];
__device__ __half g_wff2T[(size_t)HS * FF];
__device__ __half g_qkvh [(size_t)MM * H3];
__device__ __half g_ctxh [(size_t)MM * HS];
__device__ __half g_aoh  [(size_t)MM * HS];
__device__ float  g_x1   [(size_t)MM * HS];
__device__ __half g_x1h  [(size_t)MM * HS];
__device__ __half g_h1h  [(size_t)MM * FF];
__device__ __half g_f2h  [(size_t)MM * HS];

// ================= helpers ==================================================
__device__ __forceinline__ uint32_t smem_u32(const void* p) {
    uint32_t a;
    asm("{ .reg .u64 t; cvta.to.shared.u64 t, %1; cvt.u32.u64 %0, t; }" : "=r"(a) : "l"(p));
    return a;
}
__device__ __forceinline__ void cp16(uint32_t s, const void* g) {
    asm volatile("cp.async.cg.shared.global [%0], [%1], 16;" :: "r"(s), "l"(g) : "memory");
}
__device__ __forceinline__ void cp_commit() {
    asm volatile("cp.async.commit_group;" ::: "memory");
}
template<int N> __device__ __forceinline__ void cp_wait() {
    asm volatile("cp.async.wait_group %0;" :: "n"(N) : "memory");
}
__device__ __forceinline__ void mma_f16(float c[4], const uint32_t a[4], const uint32_t b[2]) {
    asm volatile(
        "mma.sync.aligned.m16n8k16.row.col.f32.f16.f16.f32 "
        "{%0,%1,%2,%3}, {%4,%5,%6,%7}, {%8,%9}, {%0,%1,%2,%3};"
        : "+f"(c[0]), "+f"(c[1]), "+f"(c[2]), "+f"(c[3])
        : "r"(a[0]), "r"(a[1]), "r"(a[2]), "r"(a[3]), "r"(b[0]), "r"(b[1]));
}
__device__ __forceinline__ void ldmx4(uint32_t r[4], uint32_t addr) {
    asm volatile("ldmatrix.sync.aligned.m8n8.x4.shared.b16 {%0,%1,%2,%3}, [%4];"
                 : "=r"(r[0]), "=r"(r[1]), "=r"(r[2]), "=r"(r[3]) : "r"(addr));
}
__device__ __forceinline__ void ldmx2t(uint32_t& b0, uint32_t& b1, uint32_t addr) {
    asm volatile("ldmatrix.sync.aligned.m8n8.x2.trans.shared.b16 {%0,%1}, [%2];"
                 : "=r"(b0), "=r"(b1) : "r"(addr));
}

// ---------------- pre-pass: fp32 -> fp16 ----------------------------------
__global__ void __launch_bounds__(256)
f2h_kernel(const float* __restrict__ in, __half* __restrict__ out, int n4)
{
    int i = blockIdx.x * 256 + threadIdx.x;
    if (i < n4) {
        float4 v = *(const float4*)(in + (size_t)i * 4);
        __half2 h0 = __floats2half2_rn(v.x, v.y);
        __half2 h1 = __floats2half2_rn(v.z, v.w);
        *(uint2*)(out + (size_t)i * 4) = make_uint2(*(uint32_t*)&h0, *(uint32_t*)&h1);
    }
}

// W[K][N] fp32 -> WT[N][K] fp16.  grid (N/32, K/32), block (32,8)
__global__ void __launch_bounds__(256)
transpose_h(const float* __restrict__ W, __half* __restrict__ WT, int K, int N)
{
    __shared__ float t[32][33];
    const int n0 = blockIdx.x * 32, k0 = blockIdx.y * 32;
    const int tx = threadIdx.x, ty = threadIdx.y;
#pragma unroll
    for (int i = 0; i < 4; i++)
        t[ty + i * 8][tx] = W[(size_t)(k0 + ty + i * 8) * N + n0 + tx];
    __syncthreads();
#pragma unroll
    for (int i = 0; i < 4; i++)
        WT[(size_t)(n0 + ty + i * 8) * K + k0 + tx] = __float2half_rn(t[tx][ty + i * 8]);
}

// ---------------- fp16 mma GEMM, ldmatrix fragments ------------------------
#define PITCH  40
#define AST    (128 * PITCH)
#define STG_H  (2 * AST)
#define STAGES 4
#define GH_SMEM_BYTES (STAGES * STG_H * 2)

template<int GELU, int OUTH>
__global__ void __launch_bounds__(256, 2)
gemm_h(const __half* __restrict__ A, const __half* __restrict__ WT,
       const float* __restrict__ bias,
       float* __restrict__ Cf, __half* __restrict__ Ch,
       int N, int K)
{
    extern __shared__ __half hsm[];
    const uint32_t sbase = smem_u32(hsm);

    const int tid  = threadIdx.x;
    const int warp = tid >> 5;
    const int lane = tid & 31;
    const int g    = lane >> 2;
    const int t    = lane & 3;
    const int wm   = warp >> 2;
    const int wn   = warp & 3;
    const int row0 = blockIdx.y * 128;
    const int col0 = blockIdx.x * 128;
    const int KT   = K >> 5;

    const __half* Ab = A  + (size_t)row0 * K;
    const __half* Bb = WT + (size_t)col0 * K;

    const int cr = tid >> 2;
    const int cc = tid & 3;

    const int lm_arow = wm * 64 + (lane & 15);
    const int lm_acol = (lane >> 4) * 8;
    const int lm_brow = wn * 32 + (lane & 7) + ((lane >> 4) << 3);
    const int lm_bcol = ((lane >> 3) & 1) * 8;

    float acc[4][4][4];
#pragma unroll
    for (int mi = 0; mi < 4; mi++)
#pragma unroll
        for (int ni = 0; ni < 4; ni++)
#pragma unroll
            for (int q = 0; q < 4; q++) acc[mi][ni][q] = 0.f;

#pragma unroll
    for (int s = 0; s < 3; s++) {
        const uint32_t sa = sbase + s * STG_H * 2;
        const int k0 = s * 32;
#pragma unroll
        for (int j = 0; j < 2; j++) {
            int r = cr + j * 64;
            cp16(sa + (r * PITCH + cc * 8) * 2,       Ab + (size_t)r * K + k0 + cc * 8);
            cp16(sa + (AST + r * PITCH + cc * 8) * 2, Bb + (size_t)r * K + k0 + cc * 8);
        }
        cp_commit();
    }

    for (int it = 0; it < KT; it++) {
        if (it + 2 < KT)      cp_wait<2>();
        else if (it + 1 < KT) cp_wait<1>();
        else                  cp_wait<0>();
        __syncthreads();

        if (it + 3 < KT) {
            const int s = (it + 3) & 3;
            const uint32_t sa = sbase + s * STG_H * 2;
            const int k0 = (it + 3) * 32;
#pragma unroll
            for (int j = 0; j < 2; j++) {
                int r = cr + j * 64;
                cp16(sa + (r * PITCH + cc * 8) * 2,       Ab + (size_t)r * K + k0 + cc * 8);
                cp16(sa + (AST + r * PITCH + cc * 8) * 2, Bb + (size_t)r * K + k0 + cc * 8);
            }
            cp_commit();
        }

        const uint32_t cAu = sbase + (uint32_t)((it & 3) * STG_H) * 2;
        const uint32_t cBu = cAu + AST * 2;
#pragma unroll
        for (int ks = 0; ks < 2; ks++) {
            const int kb = ks * 16;
            uint32_t af[4][4], bf[4][2];
#pragma unroll
            for (int mi = 0; mi < 4; mi++)
                ldmx4(af[mi], cAu + (((lm_arow + mi * 16) * PITCH) + kb + lm_acol) * 2);
#pragma unroll
            for (int nip = 0; nip < 2; nip++) {
                uint32_t r[4];
                ldmx4(r, cBu + (((lm_brow + nip * 16) * PITCH) + kb + lm_bcol) * 2);
                bf[nip * 2][0]     = r[0];
                bf[nip * 2][1]     = r[1];
                bf[nip * 2 + 1][0] = r[2];
                bf[nip * 2 + 1][1] = r[3];
            }
#pragma unroll
            for (int mi = 0; mi < 4; mi++)
#pragma unroll
                for (int ni = 0; ni < 4; ni++)
                    mma_f16(acc[mi][ni], af[mi], bf[ni]);
        }
    }

#pragma unroll
    for (int mi = 0; mi < 4; mi++) {
        const int r0 = row0 + wm * 64 + mi * 16 + g;
#pragma unroll
        for (int ni = 0; ni < 4; ni++) {
            const int c = col0 + wn * 32 + ni * 8 + 2 * t;
            const float b0 = __ldg(bias + c);
            const float b1 = __ldg(bias + c + 1);
            float v0 = acc[mi][ni][0] + b0;
            float v1 = acc[mi][ni][1] + b1;
            float v2 = acc[mi][ni][2] + b0;
            float v3 = acc[mi][ni][3] + b1;
            if (GELU) {
                v0 = 0.5f * v0 * (1.0f + erff(v0 * 0.70710678118654752f));
                v1 = 0.5f * v1 * (1.0f + erff(v1 * 0.70710678118654752f));
                v2 = 0.5f * v2 * (1.0f + erff(v2 * 0.70710678118654752f));
                v3 = 0.5f * v3 * (1.0f + erff(v3 * 0.70710678118654752f));
            }
            if (OUTH) {
                *(__half2*)(Ch + (size_t)r0 * N + c)       = __floats2half2_rn(v0, v1);
                *(__half2*)(Ch + (size_t)(r0 + 8) * N + c) = __floats2half2_rn(v2, v3);
            } else {
                *(float2*)(Cf + (size_t)r0 * N + c)       = make_float2(v0, v1);
                *(float2*)(Cf + (size_t)(r0 + 8) * N + c) = make_float2(v2, v3);
            }
        }
    }
}

// ---------------- fp16 tensor-core flash attention --------------------------
#define HP 72
#define AQ_OFF 0
#define AK_OFF (128 * HP)
#define AV_OFF (128 * HP + 2 * 64 * HP)
#define ATTN_SMEM_BYTES ((128 * HP + 4 * 64 * HP) * 2)

__global__ void __launch_bounds__(256)
attn_mma(const __half* __restrict__ qkvh, __half* __restrict__ ctxh)
{
    extern __shared__ __half hsm[];
    __half* sQ = hsm + AQ_OFF;
    const uint32_t sb = smem_u32(hsm);

    const int tid  = threadIdx.x;
    const int warp = tid >> 5;
    const int lane = tid & 31;
    const int g    = lane >> 2;
    const int t    = lane & 3;
    const int m0   = warp * 16;
    const int l16  = lane & 15;

    const int q0 = blockIdx.x * 128;
    const int h  = blockIdx.y;
    const int b  = blockIdx.z;

    const __half* Qg = qkvh + ((size_t)(b * SS) + q0) * H3 + h * HD;
    const __half* Kg = qkvh + (size_t)(b * SS) * H3 + HS     + h * HD;
    const __half* Vg = qkvh + (size_t)(b * SS) * H3 + 2 * HS + h * HD;

    const int lm_krow = (lane & 7) + ((lane >> 4) << 3);
    const int lm_kcol = ((lane >> 3) & 1) * 8;

#pragma unroll
    for (int it = 0; it < 4; it++) {
        int item = tid + it * 256;
        int r = item >> 3, c = item & 7;
        *(uint4*)(sQ + r * HP + c * 8) = *(const uint4*)(Qg + (size_t)r * H3 + c * 8);
    }

    {
        const uint32_t ka = sb + AK_OFF * 2;
        const uint32_t va = sb + AV_OFF * 2;
#pragma unroll
        for (int it = 0; it < 2; it++) {
            int item = tid + it * 256;
            int j = item >> 3, c = item & 7;
            const size_t go = (size_t)j * H3 + c * 8;
            cp16(ka + (j * HP + c * 8) * 2, Kg + go);
            cp16(va + (j * HP + c * 8) * 2, Vg + go);
        }
        cp_commit();
    }
    __syncthreads();

    uint32_t qf[4][4];
#pragma unroll
    for (int kb = 0; kb < 4; kb++) {
        qf[kb][0] = *(const uint32_t*)(sQ + (m0 + g)     * HP + kb * 16 + 2 * t);
        qf[kb][1] = *(const uint32_t*)(sQ + (m0 + g + 8) * HP + kb * 16 + 2 * t);
        qf[kb][2] = *(const uint32_t*)(sQ + (m0 + g)     * HP + kb * 16 + 8 + 2 * t);
        qf[kb][3] = *(const uint32_t*)(sQ + (m0 + g + 8) * HP + kb * 16 + 8 + 2 * t);
    }

    float mrow0 = -1e30f, mrow1 = -1e30f;
    float lrow0 = 0.f,    lrow1 = 0.f;
    float o[8][4];
#pragma unroll
    for (int ni = 0; ni < 8; ni++)
#pragma unroll
        for (int q = 0; q < 4; q++) o[ni][q] = 0.f;

    const float scale = 0.125f;
    const int NT = SS / 64;

    for (int kt = 0; kt < NT; kt++) {
        cp_wait<0>();
        __syncthreads();

        const int buf = kt & 1;
        const uint32_t skb = sb + (AK_OFF + buf * 64 * HP) * 2;
        const uint32_t svb = sb + (AV_OFF + buf * 64 * HP) * 2;

        if (kt + 1 < NT) {
            const int nb = buf ^ 1;
            const uint32_t ka = sb + (AK_OFF + nb * 64 * HP) * 2;
            const uint32_t va = sb + (AV_OFF + nb * 64 * HP) * 2;
#pragma unroll
            for (int it = 0; it < 2; it++) {
                int item = tid + it * 256;
                int j = item >> 3, c = item & 7;
                const size_t go = (size_t)((kt + 1) * 64 + j) * H3 + c * 8;
                cp16(ka + (j * HP + c * 8) * 2, Kg + go);
                cp16(va + (j * HP + c * 8) * 2, Vg + go);
            }
            cp_commit();
        }

        float s_[8][4];
#pragma unroll
        for (int ni = 0; ni < 8; ni++)
#pragma unroll
            for (int q = 0; q < 4; q++) s_[ni][q] = 0.f;

#pragma unroll
        for (int kb = 0; kb < 4; kb++) {
#pragma unroll
            for (int nip = 0; nip < 4; nip++) {
                uint32_t r[4];
                ldmx4(r, skb + (((nip * 16 + lm_krow) * HP) + kb * 16 + lm_kcol) * 2);
                uint32_t bf0[2] = { r[0], r[1] };
                uint32_t bf1[2] = { r[2], r[3] };
                mma_f16(s_[nip * 2],     qf[kb], bf0);
                mma_f16(s_[nip * 2 + 1], qf[kb], bf1);
            }
        }

        float mn0 = -1e30f, mn1 = -1e30f;
#pragma unroll
        for (int ni = 0; ni < 8; ni++) {
            s_[ni][0] *= scale; s_[ni][1] *= scale;
            s_[ni][2] *= scale; s_[ni][3] *= scale;
            mn0 = fmaxf(mn0, fmaxf(s_[ni][0], s_[ni][1]));
            mn1 = fmaxf(mn1, fmaxf(s_[ni][2], s_[ni][3]));
        }
        mn0 = fmaxf(mn0, __shfl_xor_sync(0xffffffffu, mn0, 1));
        mn0 = fmaxf(mn0, __shfl_xor_sync(0xffffffffu, mn0, 2));
        mn1 = fmaxf(mn1, __shfl_xor_sync(0xffffffffu, mn1, 1));
        mn1 = fmaxf(mn1, __shfl_xor_sync(0xffffffffu, mn1, 2));

        const float mnew0 = fmaxf(mrow0, mn0);
        const float mnew1 = fmaxf(mrow1, mn1);
        const float a0 = __expf(mrow0 - mnew0);
        const float a1 = __expf(mrow1 - mnew1);
        mrow0 = mnew0; mrow1 = mnew1;

        float ladd0 = 0.f, ladd1 = 0.f;
#pragma unroll
        for (int ni = 0; ni < 8; ni++) {
            s_[ni][0] = __expf(s_[ni][0] - mnew0);
            s_[ni][1] = __expf(s_[ni][1] - mnew0);
            s_[ni][2] = __expf(s_[ni][2] - mnew1);
            s_[ni][3] = __expf(s_[ni][3] - mnew1);
            ladd0 += s_[ni][0] + s_[ni][1];
            ladd1 += s_[ni][2] + s_[ni][3];
            o[ni][0] *= a0; o[ni][1] *= a0;
            o[ni][2] *= a1; o[ni][3] *= a1;
        }
        ladd0 += __shfl_xor_sync(0xffffffffu, ladd0, 1);
        ladd0 += __shfl_xor_sync(0xffffffffu, ladd0, 2);
        ladd1 += __shfl_xor_sync(0xffffffffu, ladd1, 1);
        ladd1 += __shfl_xor_sync(0xffffffffu, ladd1, 2);
        lrow0 = lrow0 * a0 + ladd0;
        lrow1 = lrow1 * a1 + ladd1;

#pragma unroll
        for (int kb = 0; kb < 4; kb++) {
            uint32_t af[4];
            {
                __half2 h0 = __floats2half2_rn(s_[2 * kb][0],     s_[2 * kb][1]);
                __half2 h1 = __floats2half2_rn(s_[2 * kb][2],     s_[2 * kb][3]);
                __half2 h2 = __floats2half2_rn(s_[2 * kb + 1][0], s_[2 * kb + 1][1]);
                __half2 h3 = __floats2half2_rn(s_[2 * kb + 1][2], s_[2 * kb + 1][3]);
                af[0] = *(uint32_t*)&h0;
                af[1] = *(uint32_t*)&h1;
                af[2] = *(uint32_t*)&h2;
                af[3] = *(uint32_t*)&h3;
            }
            const uint32_t rowaddr = svb + ((kb * 16 + l16) * HP) * 2;
#pragma unroll
            for (int ni = 0; ni < 8; ni++) {
                uint32_t bf0, bf1;
                ldmx2t(bf0, bf1, rowaddr + ni * 16);
                uint32_t bf[2] = { bf0, bf1 };
                mma_f16(o[ni], af, bf);
            }
        }
    }

    const float inv0 = 1.0f / lrow0;
    const float inv1 = 1.0f / lrow1;
    const int qr0 = q0 + m0 + g;
    __half* dst0 = ctxh + ((size_t)(b * SS) + qr0)     * HS + h * HD;
    __half* dst1 = ctxh + ((size_t)(b * SS) + qr0 + 8) * HS + h * HD;
#pragma unroll
    for (int ni = 0; ni < 8; ni++) {
        const int c = ni * 8 + 2 * t;
        *(__half2*)(dst0 + c) = __floats2half2_rn(o[ni][0] * inv0, o[ni][1] * inv0);
        *(__half2*)(dst1 + c) = __floats2half2_rn(o[ni][2] * inv1, o[ni][3] * inv1);
    }
}

// ---------------- residual add (fp16 a) + LayerNorm ------------------------
template<int WH>
__global__ void __launch_bounds__(256)
addln_kernel(const __half* __restrict__ a, const float* __restrict__ res,
             const float* __restrict__ g, const float* __restrict__ bb,
             float* __restrict__ outf, __half* __restrict__ outh)
{
    __shared__ float wsum[8], wsq[8];
    __shared__ float s_mu, s_rstd;

    const int row = blockIdx.x;
    const int tid = threadIdx.x;
    const __half* ar = a   + (size_t)row * HS;
    const float*  rr = res + (size_t)row * HS;

    float v[3];
    float sum = 0.f, sq = 0.f;
#pragma unroll
    for (int i = 0; i < 3; i++) {
        int idx = tid + i * 256;
        v[i] = __half2float(ar[idx]) + rr[idx];
        sum += v[i];
        sq  += v[i] * v[i];
    }
#pragma unroll
    for (int off = 16; off > 0; off >>= 1) {
        sum += __shfl_down_sync(0xffffffffu, sum, off);
        sq  += __shfl_down_sync(0xffffffffu, sq,  off);
    }
    if ((tid & 31) == 0) { wsum[tid >> 5] = sum; wsq[tid >> 5] = sq; }
    __syncthreads();
    if (tid == 0) {
        float s = 0.f, q = 0.f;
#pragma unroll
        for (int i = 0; i < 8; i++) { s += wsum[i]; q += wsq[i]; }
        float mu  = s * (1.f / HS);
        float var = q * (1.f / HS) - mu * mu;
        s_mu = mu;
        s_rstd = rsqrtf(fmaxf(var, 0.f) + 1e-12f);
    }
    __syncthreads();
    float mu = s_mu, rstd = s_rstd;
#pragma unroll
    for (int i = 0; i < 3; i++) {
        int idx = tid + i * 256;
        float r = (v[i] - mu) * rstd * g[idx] + bb[idx];
        outf[(size_t)row * HS + idx] = r;
        if (WH) outh[(size_t)row * HS + idx] = __float2half_rn(r);
    }
}

// ---------------- launch ---------------------------------------------------
extern "C" void kernel_launch(void* const* d_in, const int* in_sizes, int n_in,
                              void* d_out, int out_size)
{
    const float* x     = (const float*)d_in[0];
    const float* w_qkv = (const float*)d_in[1];
    const float* b_qkv = (const float*)d_in[2];
    const float* w_out = (const float*)d_in[3];
    const float* b_out = (const float*)d_in[4];
    const float* w_ff1 = (const float*)d_in[5];
    const float* b_ff1 = (const float*)d_in[6];
    const float* w_ff2 = (const float*)d_in[7];
    const float* b_ff2 = (const float*)d_in[8];
    const float* g1    = (const float*)d_in[9];
    const float* be1   = (const float*)d_in[10];
    const float* g2    = (const float*)d_in[11];
    const float* be2   = (const float*)d_in[12];
    float* out = (float*)d_out;

    __half *xh, *wqkvT, *woutT, *wff1T, *wff2T, *qkvh, *ctxh, *aoh, *x1h, *h1h, *f2h;
    float *x1;
    cudaGetSymbolAddress((void**)&xh,    g_xh);
    cudaGetSymbolAddress((void**)&wqkvT, g_wqkvT);
    cudaGetSymbolAddress((void**)&woutT, g_woutT);
    cudaGetSymbolAddress((void**)&wff1T, g_wff1T);
    cudaGetSymbolAddress((void**)&wff2T, g_wff2T);
    cudaGetSymbolAddress((void**)&qkvh,  g_qkvh);
    cudaGetSymbolAddress((void**)&ctxh,  g_ctxh);
    cudaGetSymbolAddress((void**)&aoh,   g_aoh);
    cudaGetSymbolAddress((void**)&x1h,   g_x1h);
    cudaGetSymbolAddress((void**)&h1h,   g_h1h);
    cudaGetSymbolAddress((void**)&f2h,   g_f2h);
    cudaGetSymbolAddress((void**)&x1,    g_x1);

    cudaFuncSetAttribute(attn_mma,
                         cudaFuncAttributeMaxDynamicSharedMemorySize, ATTN_SMEM_BYTES);
    cudaFuncSetAttribute(gemm_h<0,1>, cudaFuncAttributeMaxDynamicSharedMemorySize, GH_SMEM_BYTES);
    cudaFuncSetAttribute(gemm_h<1,1>, cudaFuncAttributeMaxDynamicSharedMemorySize, GH_SMEM_BYTES);

    dim3 tb(32, 8);

    // launch order arranged so index 4 = attn_mma, index 5 = gemm_h(out-proj)
    // (the ncu -s/-c window lands there instead of on a transpose)
    f2h_kernel<<<(MM * HS / 4 + 255) / 256, 256>>>(x, xh, MM * HS / 4);           // 0
    transpose_h<<<dim3(H3 / 32, HS / 32), tb>>>(w_qkv, wqkvT, HS, H3);            // 1
    transpose_h<<<dim3(HS / 32, HS / 32), tb>>>(w_out, woutT, HS, HS);            // 2

    gemm_h<0,1><<<dim3(H3 / 128, MM / 128), 256, GH_SMEM_BYTES>>>(                // 3
        xh, wqkvT, b_qkv, nullptr, qkvh, H3, HS);

    attn_mma<<<dim3(SS / 128, NH, BB), 256, ATTN_SMEM_BYTES>>>(qkvh, ctxh);       // 4

    gemm_h<0,1><<<dim3(HS / 128, MM / 128), 256, GH_SMEM_BYTES>>>(                // 5
        ctxh, woutT, b_out, nullptr, aoh, HS, HS);

    addln_kernel<1><<<MM, 256>>>(aoh, x, g1, be1, x1, x1h);                       // 6

    transpose_h<<<dim3(FF / 32, HS / 32), tb>>>(w_ff1, wff1T, HS, FF);            // 7
    gemm_h<1,1><<<dim3(FF / 128, MM / 128), 256, GH_SMEM_BYTES>>>(                // 8
        x1h, wff1T, b_ff1, nullptr, h1h, FF, HS);

    transpose_h<<<dim3(HS / 32, FF / 32), tb>>>(w_ff2, wff2T, FF, HS);            // 9
    gemm_h<0,1><<<dim3(HS / 128, MM / 128), 256, GH_SMEM_BYTES>>>(                // 10
        h1h, wff2T, b_ff2, nullptr, f2h, HS, FF);

    addln_kernel<0><<<MM, 256>>>(f2h, x1, g2, be2, out, nullptr);                 // 11
}

// round 9
// speedup vs baseline: 6.9722x; 1.0609x over previous
#include <cuda_runtime.h>
#include <cuda_fp16.h>
#include <math.h>
#include <stdint.h>

#define HS   768
#define NH   12
#define HD   64
#define FF   3072
#define BB   4
#define SS   2048
#define MM   (BB*SS)     /* 8192 rows */
#define H3   (3*HS)      /* 2304 */

// ---------------- scratch (device globals, no allocation) ----------------
__device__ __half g_xh   [(size_t)MM * HS];
__device__ __half g_wqkvT[(size_t)H3 * HS];
__device__ __half g_woutT[(size_t)HS * HS];
__device__ __half g_wff1T[(size_t)FF * HS];
__device__ __half g_wff2T[(size_t)HS * FF];
__device__ __half g_qkvh [(size_t)MM * H3];
__device__ __half g_ctxh [(size_t)MM * HS];
__device__ __half g_aoh  [(size_t)MM * HS];
__device__ float  g_x1   [(size_t)MM * HS];
__device__ __half g_x1h  [(size_t)MM * HS];
__device__ __half g_h1h  [(size_t)MM * FF];
__device__ __half g_f2h  [(size_t)MM * HS];

// ================= helpers ==================================================
__device__ __forceinline__ uint32_t smem_u32(const void* p) {
    uint32_t a;
    asm("{ .reg .u64 t; cvta.to.shared.u64 t, %1; cvt.u32.u64 %0, t; }" : "=r"(a) : "l"(p));
    return a;
}
__device__ __forceinline__ void cp16(uint32_t s, const void* g) {
    asm volatile("cp.async.cg.shared.global [%0], [%1], 16;" :: "r"(s), "l"(g) : "memory");
}
__device__ __forceinline__ void cp_commit() {
    asm volatile("cp.async.commit_group;" ::: "memory");
}
template<int N> __device__ __forceinline__ void cp_wait() {
    asm volatile("cp.async.wait_group %0;" :: "n"(N) : "memory");
}
__device__ __forceinline__ void mma_f16(float c[4], const uint32_t a[4], const uint32_t b[2]) {
    asm volatile(
        "mma.sync.aligned.m16n8k16.row.col.f32.f16.f16.f32 "
        "{%0,%1,%2,%3}, {%4,%5,%6,%7}, {%8,%9}, {%0,%1,%2,%3};"
        : "+f"(c[0]), "+f"(c[1]), "+f"(c[2]), "+f"(c[3])
        : "r"(a[0]), "r"(a[1]), "r"(a[2]), "r"(a[3]), "r"(b[0]), "r"(b[1]));
}
__device__ __forceinline__ void ldmx4(uint32_t r[4], uint32_t addr) {
    asm volatile("ldmatrix.sync.aligned.m8n8.x4.shared.b16 {%0,%1,%2,%3}, [%4];"
                 : "=r"(r[0]), "=r"(r[1]), "=r"(r[2]), "=r"(r[3]) : "r"(addr));
}
__device__ __forceinline__ void ldmx2t(uint32_t& b0, uint32_t& b1, uint32_t addr) {
    asm volatile("ldmatrix.sync.aligned.m8n8.x2.trans.shared.b16 {%0,%1}, [%2];"
                 : "=r"(b0), "=r"(b1) : "r"(addr));
}

// ---------------- pre-pass: fp32 -> fp16 ----------------------------------
__global__ void __launch_bounds__(256)
f2h_kernel(const float* __restrict__ in, __half* __restrict__ out, int n4)
{
    int i = blockIdx.x * 256 + threadIdx.x;
    if (i < n4) {
        float4 v = *(const float4*)(in + (size_t)i * 4);
        __half2 h0 = __floats2half2_rn(v.x, v.y);
        __half2 h1 = __floats2half2_rn(v.z, v.w);
        *(uint2*)(out + (size_t)i * 4) = make_uint2(*(uint32_t*)&h0, *(uint32_t*)&h1);
    }
}

// W[K][N] fp32 -> WT[N][K] fp16.  grid (N/32, K/32), block (32,8)
__global__ void __launch_bounds__(256)
transpose_h(const float* __restrict__ W, __half* __restrict__ WT, int K, int N)
{
    __shared__ float t[32][33];
    const int n0 = blockIdx.x * 32, k0 = blockIdx.y * 32;
    const int tx = threadIdx.x, ty = threadIdx.y;
#pragma unroll
    for (int i = 0; i < 4; i++)
        t[ty + i * 8][tx] = W[(size_t)(k0 + ty + i * 8) * N + n0 + tx];
    __syncthreads();
#pragma unroll
    for (int i = 0; i < 4; i++)
        WT[(size_t)(n0 + ty + i * 8) * K + k0 + tx] = __float2half_rn(t[tx][ty + i * 8]);
}

// ---------------- fp16 mma GEMM: BK=64, 3-stage cp.async -------------------
// BM=BN=128, BK=64, 256 threads (8 warps 2x4, warp tile 64x32).
#define PITCH  72                        /* halfs per 64-half row (+8 pad) */
#define AST    (128 * PITCH)             /* halfs per A (or B) stage tile */
#define STG_H  (2 * AST)                 /* halfs per stage (A+B) */
#define STAGES 3
#define GH_SMEM_BYTES (STAGES * STG_H * 2)   /* 110592 B */

template<int GELU, int OUTH>
__global__ void __launch_bounds__(256, 2)
gemm_h(const __half* __restrict__ A, const __half* __restrict__ WT,
       const float* __restrict__ bias,
       float* __restrict__ Cf, __half* __restrict__ Ch,
       int N, int K)
{
    extern __shared__ __half hsm[];
    const uint32_t sbase = smem_u32(hsm);

    const int tid  = threadIdx.x;
    const int warp = tid >> 5;
    const int lane = tid & 31;
    const int g    = lane >> 2;
    const int t    = lane & 3;
    const int wm   = warp >> 2;
    const int wn   = warp & 3;
    const int row0 = blockIdx.y * 128;
    const int col0 = blockIdx.x * 128;
    const int KT   = K >> 6;             /* K/64 iterations */

    const __half* Ab = A  + (size_t)row0 * K;
    const __half* Bb = WT + (size_t)col0 * K;

    const int lm_arow = wm * 64 + (lane & 15);
    const int lm_acol = (lane >> 4) * 8;
    const int lm_brow = wn * 32 + (lane & 7) + ((lane >> 4) << 3);
    const int lm_bcol = ((lane >> 3) & 1) * 8;

    float acc[4][4][4];
#pragma unroll
    for (int mi = 0; mi < 4; mi++)
#pragma unroll
        for (int ni = 0; ni < 4; ni++)
#pragma unroll
            for (int q = 0; q < 4; q++) acc[mi][ni][q] = 0.f;

    // prologue: issue stages 0,1 (8 cp16 per thread per stage)
#pragma unroll
    for (int s = 0; s < 2; s++) {
        const uint32_t sa = sbase + s * STG_H * 2;
        const int k0 = s * 64;
#pragma unroll
        for (int j = 0; j < 4; j++) {
            int item = tid + j * 256;
            int r = item >> 3, c = item & 7;
            cp16(sa + (r * PITCH + c * 8) * 2,       Ab + (size_t)r * K + k0 + c * 8);
            cp16(sa + (AST + r * PITCH + c * 8) * 2, Bb + (size_t)r * K + k0 + c * 8);
        }
        cp_commit();
    }

    int stg = 0;
    for (int it = 0; it < KT; it++) {
        if (it + 1 < KT) cp_wait<1>();
        else             cp_wait<0>();
        __syncthreads();

        if (it + 2 < KT) {
            int s = stg + 2; if (s >= STAGES) s -= STAGES;
            const uint32_t sa = sbase + s * STG_H * 2;
            const int k0 = (it + 2) * 64;
#pragma unroll
            for (int j = 0; j < 4; j++) {
                int item = tid + j * 256;
                int r = item >> 3, c = item & 7;
                cp16(sa + (r * PITCH + c * 8) * 2,       Ab + (size_t)r * K + k0 + c * 8);
                cp16(sa + (AST + r * PITCH + c * 8) * 2, Bb + (size_t)r * K + k0 + c * 8);
            }
            cp_commit();
        }

        const uint32_t cAu = sbase + (uint32_t)(stg * STG_H) * 2;
        const uint32_t cBu = cAu + AST * 2;
#pragma unroll
        for (int ks = 0; ks < 4; ks++) {
            const int kb = ks * 16;
            uint32_t af[4][4], bf[4][2];
#pragma unroll
            for (int mi = 0; mi < 4; mi++)
                ldmx4(af[mi], cAu + (((lm_arow + mi * 16) * PITCH) + kb + lm_acol) * 2);
#pragma unroll
            for (int nip = 0; nip < 2; nip++) {
                uint32_t r[4];
                ldmx4(r, cBu + (((lm_brow + nip * 16) * PITCH) + kb + lm_bcol) * 2);
                bf[nip * 2][0]     = r[0];
                bf[nip * 2][1]     = r[1];
                bf[nip * 2 + 1][0] = r[2];
                bf[nip * 2 + 1][1] = r[3];
            }
#pragma unroll
            for (int mi = 0; mi < 4; mi++)
#pragma unroll
                for (int ni = 0; ni < 4; ni++)
                    mma_f16(acc[mi][ni], af[mi], bf[ni]);
        }
        if (++stg == STAGES) stg = 0;
    }

#pragma unroll
    for (int mi = 0; mi < 4; mi++) {
        const int r0 = row0 + wm * 64 + mi * 16 + g;
#pragma unroll
        for (int ni = 0; ni < 4; ni++) {
            const int c = col0 + wn * 32 + ni * 8 + 2 * t;
            const float b0 = __ldg(bias + c);
            const float b1 = __ldg(bias + c + 1);
            float v0 = acc[mi][ni][0] + b0;
            float v1 = acc[mi][ni][1] + b1;
            float v2 = acc[mi][ni][2] + b0;
            float v3 = acc[mi][ni][3] + b1;
            if (GELU) {
                v0 = 0.5f * v0 * (1.0f + erff(v0 * 0.70710678118654752f));
                v1 = 0.5f * v1 * (1.0f + erff(v1 * 0.70710678118654752f));
                v2 = 0.5f * v2 * (1.0f + erff(v2 * 0.70710678118654752f));
                v3 = 0.5f * v3 * (1.0f + erff(v3 * 0.70710678118654752f));
            }
            if (OUTH) {
                *(__half2*)(Ch + (size_t)r0 * N + c)       = __floats2half2_rn(v0, v1);
                *(__half2*)(Ch + (size_t)(r0 + 8) * N + c) = __floats2half2_rn(v2, v3);
            } else {
                *(float2*)(Cf + (size_t)r0 * N + c)       = make_float2(v0, v1);
                *(float2*)(Cf + (size_t)(r0 + 8) * N + c) = make_float2(v2, v3);
            }
        }
    }
}

// ---------------- fp16 tensor-core flash attention --------------------------
#define HP 72
#define AQ_OFF 0
#define AK_OFF (128 * HP)
#define AV_OFF (128 * HP + 2 * 64 * HP)
#define ATTN_SMEM_BYTES ((128 * HP + 4 * 64 * HP) * 2)

__global__ void __launch_bounds__(256)
attn_mma(const __half* __restrict__ qkvh, __half* __restrict__ ctxh)
{
    extern __shared__ __half hsm[];
    __half* sQ = hsm + AQ_OFF;
    const uint32_t sb = smem_u32(hsm);

    const int tid  = threadIdx.x;
    const int warp = tid >> 5;
    const int lane = tid & 31;
    const int g    = lane >> 2;
    const int t    = lane & 3;
    const int m0   = warp * 16;
    const int l16  = lane & 15;

    const int q0 = blockIdx.x * 128;
    const int h  = blockIdx.y;
    const int b  = blockIdx.z;

    const __half* Qg = qkvh + ((size_t)(b * SS) + q0) * H3 + h * HD;
    const __half* Kg = qkvh + (size_t)(b * SS) * H3 + HS     + h * HD;
    const __half* Vg = qkvh + (size_t)(b * SS) * H3 + 2 * HS + h * HD;

    const int lm_krow = (lane & 7) + ((lane >> 4) << 3);
    const int lm_kcol = ((lane >> 3) & 1) * 8;

#pragma unroll
    for (int it = 0; it < 4; it++) {
        int item = tid + it * 256;
        int r = item >> 3, c = item & 7;
        *(uint4*)(sQ + r * HP + c * 8) = *(const uint4*)(Qg + (size_t)r * H3 + c * 8);
    }

    {
        const uint32_t ka = sb + AK_OFF * 2;
        const uint32_t va = sb + AV_OFF * 2;
#pragma unroll
        for (int it = 0; it < 2; it++) {
            int item = tid + it * 256;
            int j = item >> 3, c = item & 7;
            const size_t go = (size_t)j * H3 + c * 8;
            cp16(ka + (j * HP + c * 8) * 2, Kg + go);
            cp16(va + (j * HP + c * 8) * 2, Vg + go);
        }
        cp_commit();
    }
    __syncthreads();

    uint32_t qf[4][4];
#pragma unroll
    for (int kb = 0; kb < 4; kb++) {
        qf[kb][0] = *(const uint32_t*)(sQ + (m0 + g)     * HP + kb * 16 + 2 * t);
        qf[kb][1] = *(const uint32_t*)(sQ + (m0 + g + 8) * HP + kb * 16 + 2 * t);
        qf[kb][2] = *(const uint32_t*)(sQ + (m0 + g)     * HP + kb * 16 + 8 + 2 * t);
        qf[kb][3] = *(const uint32_t*)(sQ + (m0 + g + 8) * HP + kb * 16 + 8 + 2 * t);
    }

    float mrow0 = -1e30f, mrow1 = -1e30f;
    float lrow0 = 0.f,    lrow1 = 0.f;
    float o[8][4];
#pragma unroll
    for (int ni = 0; ni < 8; ni++)
#pragma unroll
        for (int q = 0; q < 4; q++) o[ni][q] = 0.f;

    const float scale = 0.125f;
    const int NT = SS / 64;

    for (int kt = 0; kt < NT; kt++) {
        cp_wait<0>();
        __syncthreads();

        const int buf = kt & 1;
        const uint32_t skb = sb + (AK_OFF + buf * 64 * HP) * 2;
        const uint32_t svb = sb + (AV_OFF + buf * 64 * HP) * 2;

        if (kt + 1 < NT) {
            const int nb = buf ^ 1;
            const uint32_t ka = sb + (AK_OFF + nb * 64 * HP) * 2;
            const uint32_t va = sb + (AV_OFF + nb * 64 * HP) * 2;
#pragma unroll
            for (int it = 0; it < 2; it++) {
                int item = tid + it * 256;
                int j = item >> 3, c = item & 7;
                const size_t go = (size_t)((kt + 1) * 64 + j) * H3 + c * 8;
                cp16(ka + (j * HP + c * 8) * 2, Kg + go);
                cp16(va + (j * HP + c * 8) * 2, Vg + go);
            }
            cp_commit();
        }

        float s_[8][4];
#pragma unroll
        for (int ni = 0; ni < 8; ni++)
#pragma unroll
            for (int q = 0; q < 4; q++) s_[ni][q] = 0.f;

#pragma unroll
        for (int kb = 0; kb < 4; kb++) {
#pragma unroll
            for (int nip = 0; nip < 4; nip++) {
                uint32_t r[4];
                ldmx4(r, skb + (((nip * 16 + lm_krow) * HP) + kb * 16 + lm_kcol) * 2);
                uint32_t bf0[2] = { r[0], r[1] };
                uint32_t bf1[2] = { r[2], r[3] };
                mma_f16(s_[nip * 2],     qf[kb], bf0);
                mma_f16(s_[nip * 2 + 1], qf[kb], bf1);
            }
        }

        float mn0 = -1e30f, mn1 = -1e30f;
#pragma unroll
        for (int ni = 0; ni < 8; ni++) {
            s_[ni][0] *= scale; s_[ni][1] *= scale;
            s_[ni][2] *= scale; s_[ni][3] *= scale;
            mn0 = fmaxf(mn0, fmaxf(s_[ni][0], s_[ni][1]));
            mn1 = fmaxf(mn1, fmaxf(s_[ni][2], s_[ni][3]));
        }
        mn0 = fmaxf(mn0, __shfl_xor_sync(0xffffffffu, mn0, 1));
        mn0 = fmaxf(mn0, __shfl_xor_sync(0xffffffffu, mn0, 2));
        mn1 = fmaxf(mn1, __shfl_xor_sync(0xffffffffu, mn1, 1));
        mn1 = fmaxf(mn1, __shfl_xor_sync(0xffffffffu, mn1, 2));

        const float mnew0 = fmaxf(mrow0, mn0);
        const float mnew1 = fmaxf(mrow1, mn1);
        const float a0 = __expf(mrow0 - mnew0);
        const float a1 = __expf(mrow1 - mnew1);
        mrow0 = mnew0; mrow1 = mnew1;

        float ladd0 = 0.f, ladd1 = 0.f;
#pragma unroll
        for (int ni = 0; ni < 8; ni++) {
            s_[ni][0] = __expf(s_[ni][0] - mnew0);
            s_[ni][1] = __expf(s_[ni][1] - mnew0);
            s_[ni][2] = __expf(s_[ni][2] - mnew1);
            s_[ni][3] = __expf(s_[ni][3] - mnew1);
            ladd0 += s_[ni][0] + s_[ni][1];
            ladd1 += s_[ni][2] + s_[ni][3];
            o[ni][0] *= a0; o[ni][1] *= a0;
            o[ni][2] *= a1; o[ni][3] *= a1;
        }
        ladd0 += __shfl_xor_sync(0xffffffffu, ladd0, 1);
        ladd0 += __shfl_xor_sync(0xffffffffu, ladd0, 2);
        ladd1 += __shfl_xor_sync(0xffffffffu, ladd1, 1);
        ladd1 += __shfl_xor_sync(0xffffffffu, ladd1, 2);
        lrow0 = lrow0 * a0 + ladd0;
        lrow1 = lrow1 * a1 + ladd1;

#pragma unroll
        for (int kb = 0; kb < 4; kb++) {
            uint32_t af[4];
            {
                __half2 h0 = __floats2half2_rn(s_[2 * kb][0],     s_[2 * kb][1]);
                __half2 h1 = __floats2half2_rn(s_[2 * kb][2],     s_[2 * kb][3]);
                __half2 h2 = __floats2half2_rn(s_[2 * kb + 1][0], s_[2 * kb + 1][1]);
                __half2 h3 = __floats2half2_rn(s_[2 * kb + 1][2], s_[2 * kb + 1][3]);
                af[0] = *(uint32_t*)&h0;
                af[1] = *(uint32_t*)&h1;
                af[2] = *(uint32_t*)&h2;
                af[3] = *(uint32_t*)&h3;
            }
            const uint32_t rowaddr = svb + ((kb * 16 + l16) * HP) * 2;
#pragma unroll
            for (int ni = 0; ni < 8; ni++) {
                uint32_t bf0, bf1;
                ldmx2t(bf0, bf1, rowaddr + ni * 16);
                uint32_t bf[2] = { bf0, bf1 };
                mma_f16(o[ni], af, bf);
            }
        }
    }

    const float inv0 = 1.0f / lrow0;
    const float inv1 = 1.0f / lrow1;
    const int qr0 = q0 + m0 + g;
    __half* dst0 = ctxh + ((size_t)(b * SS) + qr0)     * HS + h * HD;
    __half* dst1 = ctxh + ((size_t)(b * SS) + qr0 + 8) * HS + h * HD;
#pragma unroll
    for (int ni = 0; ni < 8; ni++) {
        const int c = ni * 8 + 2 * t;
        *(__half2*)(dst0 + c) = __floats2half2_rn(o[ni][0] * inv0, o[ni][1] * inv0);
        *(__half2*)(dst1 + c) = __floats2half2_rn(o[ni][2] * inv1, o[ni][3] * inv1);
    }
}

// ---------------- residual add (fp16 a) + LayerNorm ------------------------
template<int WH>
__global__ void __launch_bounds__(256)
addln_kernel(const __half* __restrict__ a, const float* __restrict__ res,
             const float* __restrict__ g, const float* __restrict__ bb,
             float* __restrict__ outf, __half* __restrict__ outh)
{
    __shared__ float wsum[8], wsq[8];
    __shared__ float s_mu, s_rstd;

    const int row = blockIdx.x;
    const int tid = threadIdx.x;
    const __half* ar = a   + (size_t)row * HS;
    const float*  rr = res + (size_t)row * HS;

    float v[3];
    float sum = 0.f, sq = 0.f;
#pragma unroll
    for (int i = 0; i < 3; i++) {
        int idx = tid + i * 256;
        v[i] = __half2float(ar[idx]) + rr[idx];
        sum += v[i];
        sq  += v[i] * v[i];
    }
#pragma unroll
    for (int off = 16; off > 0; off >>= 1) {
        sum += __shfl_down_sync(0xffffffffu, sum, off);
        sq  += __shfl_down_sync(0xffffffffu, sq,  off);
    }
    if ((tid & 31) == 0) { wsum[tid >> 5] = sum; wsq[tid >> 5] = sq; }
    __syncthreads();
    if (tid == 0) {
        float s = 0.f, q = 0.f;
#pragma unroll
        for (int i = 0; i < 8; i++) { s += wsum[i]; q += wsq[i]; }
        float mu  = s * (1.f / HS);
        float var = q * (1.f / HS) - mu * mu;
        s_mu = mu;
        s_rstd = rsqrtf(fmaxf(var, 0.f) + 1e-12f);
    }
    __syncthreads();
    float mu = s_mu, rstd = s_rstd;
#pragma unroll
    for (int i = 0; i < 3; i++) {
        int idx = tid + i * 256;
        float r = (v[i] - mu) * rstd * g[idx] + bb[idx];
        outf[(size_t)row * HS + idx] = r;
        if (WH) outh[(size_t)row * HS + idx] = __float2half_rn(r);
    }
}

// ---------------- launch ---------------------------------------------------
extern "C" void kernel_launch(void* const* d_in, const int* in_sizes, int n_in,
                              void* d_out, int out_size)
{
    const float* x     = (const float*)d_in[0];
    const float* w_qkv = (const float*)d_in[1];
    const float* b_qkv = (const float*)d_in[2];
    const float* w_out = (const float*)d_in[3];
    const float* b_out = (const float*)d_in[4];
    const float* w_ff1 = (const float*)d_in[5];
    const float* b_ff1 = (const float*)d_in[6];
    const float* w_ff2 = (const float*)d_in[7];
    const float* b_ff2 = (const float*)d_in[8];
    const float* g1    = (const float*)d_in[9];
    const float* be1   = (const float*)d_in[10];
    const float* g2    = (const float*)d_in[11];
    const float* be2   = (const float*)d_in[12];
    float* out = (float*)d_out;

    __half *xh, *wqkvT, *woutT, *wff1T, *wff2T, *qkvh, *ctxh, *aoh, *x1h, *h1h, *f2h;
    float *x1;
    cudaGetSymbolAddress((void**)&xh,    g_xh);
    cudaGetSymbolAddress((void**)&wqkvT, g_wqkvT);
    cudaGetSymbolAddress((void**)&woutT, g_woutT);
    cudaGetSymbolAddress((void**)&wff1T, g_wff1T);
    cudaGetSymbolAddress((void**)&wff2T, g_wff2T);
    cudaGetSymbolAddress((void**)&qkvh,  g_qkvh);
    cudaGetSymbolAddress((void**)&ctxh,  g_ctxh);
    cudaGetSymbolAddress((void**)&aoh,   g_aoh);
    cudaGetSymbolAddress((void**)&x1h,   g_x1h);
    cudaGetSymbolAddress((void**)&h1h,   g_h1h);
    cudaGetSymbolAddress((void**)&f2h,   g_f2h);
    cudaGetSymbolAddress((void**)&x1,    g_x1);

    cudaFuncSetAttribute(attn_mma,
                         cudaFuncAttributeMaxDynamicSharedMemorySize, ATTN_SMEM_BYTES);
    cudaFuncSetAttribute(gemm_h<0,1>, cudaFuncAttributeMaxDynamicSharedMemorySize, GH_SMEM_BYTES);
    cudaFuncSetAttribute(gemm_h<1,1>, cudaFuncAttributeMaxDynamicSharedMemorySize, GH_SMEM_BYTES);

    dim3 tb(32, 8);

    f2h_kernel<<<(MM * HS / 4 + 255) / 256, 256>>>(x, xh, MM * HS / 4);           // 0
    transpose_h<<<dim3(H3 / 32, HS / 32), tb>>>(w_qkv, wqkvT, HS, H3);            // 1
    transpose_h<<<dim3(HS / 32, HS / 32), tb>>>(w_out, woutT, HS, HS);            // 2

    gemm_h<0,1><<<dim3(H3 / 128, MM / 128), 256, GH_SMEM_BYTES>>>(                // 3
        xh, wqkvT, b_qkv, nullptr, qkvh, H3, HS);

    attn_mma<<<dim3(SS / 128, NH, BB), 256, ATTN_SMEM_BYTES>>>(qkvh, ctxh);       // 4

    gemm_h<0,1><<<dim3(HS / 128, MM / 128), 256, GH_SMEM_BYTES>>>(                // 5
        ctxh, woutT, b_out, nullptr, aoh, HS, HS);

    addln_kernel<1><<<MM, 256>>>(aoh, x, g1, be1, x1, x1h);                       // 6

    transpose_h<<<dim3(FF / 32, HS / 32), tb>>>(w_ff1, wff1T, HS, FF);            // 7
    gemm_h<1,1><<<dim3(FF / 128, MM / 128), 256, GH_SMEM_BYTES>>>(                // 8
        x1h, wff1T, b_ff1, nullptr, h1h, FF, HS);

    transpose_h<<<dim3(HS / 32, FF / 32), tb>>>(w_ff2, wff2T, FF, HS);            // 9
    gemm_h<0,1><<<dim3(HS / 128, MM / 128), 256, GH_SMEM_BYTES>>>(                // 10
        h1h, wff2T, b_ff2, nullptr, f2h, HS, FF);

    addln_kernel<0><<<MM, 256>>>(f2h, x1, g2, be2, out, nullptr);                 // 11
}